// round 1
// baseline (speedup 1.0000x reference)
#include <cuda_runtime.h>
#include <math.h>

// ---------------- problem constants ----------------
#define B     4
#define N     8192
#define P     2048
#define C     128
#define COUT  256
#define S     32
#define CIN   131          // 3 + C
#define R2    0.64f        // 0.8^2
#define EPSB  1e-5f
#define SPITCH 34          // smem pitch for g[c][s], even -> 8B aligned rows

#define NQ    (B*P)        // 8192 queries
#define MLPCNT ((double)(B)*(double)(P)*(double)(S))   // 262144 BN samples

// ---------------- device scratch (no cudaMalloc allowed) ----------------
__device__ float  d_newxyz[NQ * 3];
__device__ int    d_idx[NQ * S];
__device__ float  d_featsT[(size_t)B * N * C];   // (B,N,C) transposed features
__device__ float  d_Wt[CIN * COUT];              // column-major W: Wt[c*COUT+o]
__device__ float  d_mx[NQ * COUT];
__device__ float  d_mn[NQ * COUT];
__device__ double d_sums[2 * COUT];              // [0:256) sum, [256:512) sumsq
__device__ double d_sst[6];                      // shift: sum[3], sumsq[3]

// ---------------- f32x2 packed helpers ----------------
typedef unsigned long long u64;

__device__ __forceinline__ u64 pk2(float x) {
    u64 r;
    asm("mov.b64 %0, {%1, %1};" : "=l"(r) : "f"(x));
    return r;
}
__device__ __forceinline__ u64 fma2(u64 a, u64 b, u64 c) {
    u64 d;
    asm("fma.rn.f32x2 %0, %1, %2, %3;" : "=l"(d) : "l"(a), "l"(b), "l"(c));
    return d;
}
__device__ __forceinline__ void upk2(u64 v, float &lo, float &hi) {
    asm("mov.b64 {%0, %1}, %2;" : "=f"(lo), "=f"(hi) : "l"(v));
}

// ---------------- kernel 0: zero the stat accumulators ----------------
__global__ void k_zero_stats() {
    int t = threadIdx.x;
    if (t < 2 * COUT) d_sums[t] = 0.0;
    if (t < 6)        d_sst[t]  = 0.0;
}

// ---------------- kernel 1: shift GEMM + BN stats ----------------
__global__ void k_shift_stats(const float* __restrict__ ffps,
                              const float* __restrict__ wsh) {
    int i = blockIdx.x * blockDim.x + threadIdx.x;   // 0..NQ-1
    float f0 = ffps[i * 3 + 0], f1 = ffps[i * 3 + 1], f2 = ffps[i * 3 + 2];
    float x[3], xs[3], xq[3];
#pragma unroll
    for (int o = 0; o < 3; o++) {
        x[o] = wsh[o * 3 + 0] * f0 + wsh[o * 3 + 1] * f1 + wsh[o * 3 + 2] * f2;
        xs[o] = x[o];
        xq[o] = x[o] * x[o];
    }
    // warp reduce
#pragma unroll
    for (int off = 16; off > 0; off >>= 1) {
#pragma unroll
        for (int o = 0; o < 3; o++) {
            xs[o] += __shfl_down_sync(0xffffffffu, xs[o], off);
            xq[o] += __shfl_down_sync(0xffffffffu, xq[o], off);
        }
    }
    if ((threadIdx.x & 31) == 0) {
#pragma unroll
        for (int o = 0; o < 3; o++) {
            atomicAdd(&d_sst[o],     (double)xs[o]);
            atomicAdd(&d_sst[3 + o], (double)xq[o]);
        }
    }
}

// ---------------- kernel 2: apply shift BN + ReLU -> new_xyz ----------------
__global__ void k_shift_apply(const float* __restrict__ ffps,
                              const float* __restrict__ wsh,
                              const float* __restrict__ gamma,
                              const float* __restrict__ beta) {
    int i = blockIdx.x * blockDim.x + threadIdx.x;   // 0..NQ-1
    float f0 = ffps[i * 3 + 0], f1 = ffps[i * 3 + 1], f2 = ffps[i * 3 + 2];
#pragma unroll
    for (int o = 0; o < 3; o++) {
        float x = wsh[o * 3 + 0] * f0 + wsh[o * 3 + 1] * f1 + wsh[o * 3 + 2] * f2;
        double cnt = (double)NQ;
        double m = d_sst[o] / cnt;
        double v = d_sst[3 + o] / cnt - m * m;
        float a = gamma[o] * rsqrtf((float)v + EPSB);
        float val = (x - (float)m) * a + beta[o];
        d_newxyz[i * 3 + o] = fmaxf(val, 0.0f);
    }
}

// ---------------- kernel 3: transpose W (COUT,CIN) -> (CIN,COUT) ----------------
__global__ void k_transpose_w(const float* __restrict__ w) {
    int i = blockIdx.x * blockDim.x + threadIdx.x;
    if (i < COUT * CIN) {
        int o = i / CIN, c = i % CIN;
        d_Wt[c * COUT + o] = w[i];
    }
}

// ---------------- kernel 4: transpose features (B,C,N) -> (B,N,C) ----------------
__global__ void k_transpose_f(const float* __restrict__ f) {
    __shared__ float tile[32][33];
    int b  = blockIdx.z;
    int n0 = blockIdx.x * 32;
    int c0 = blockIdx.y * 32;
    const float* src = f + ((size_t)b * C + c0) * N + n0;
#pragma unroll
    for (int r = threadIdx.y; r < 32; r += 8)
        tile[r][threadIdx.x] = src[(size_t)r * N + threadIdx.x];   // tile[c][n]
    __syncthreads();
    float* dst = d_featsT + ((size_t)b * N + n0) * C + c0;
#pragma unroll
    for (int r = threadIdx.y; r < 32; r += 8)
        dst[(size_t)r * C + threadIdx.x] = tile[threadIdx.x][r];   // dst[n][c]
}

// ---------------- kernel 5: ball query (warp per query) ----------------
__global__ void k_ballquery(const float* __restrict__ bxyz) {
    int wid  = (blockIdx.x * blockDim.x + threadIdx.x) >> 5;
    int lane = threadIdx.x & 31;
    if (wid >= NQ) return;
    int b = wid >> 11;                 // / P
    float cx = d_newxyz[wid * 3 + 0];
    float cy = d_newxyz[wid * 3 + 1];
    float cz = d_newxyz[wid * 3 + 2];
    const float* xb = bxyz + (size_t)b * N * 3;
    int* outp = d_idx + (size_t)wid * S;

    int cnt = 0;
    int first = 0;
    bool found = false;
    for (int n0 = 0; n0 < N && cnt < S; n0 += 32) {
        int n = n0 + lane;
        float dx = xb[n * 3 + 0] - cx;
        float dy = xb[n * 3 + 1] - cy;
        float dz = xb[n * 3 + 2] - cz;
        float d2 = dx * dx + dy * dy + dz * dz;
        unsigned m = __ballot_sync(0xffffffffu, d2 < R2);
        if (m) {
            if (!found) { found = true; first = n0 + __ffs(m) - 1; }
            bool hit = (m >> lane) & 1u;
            int pos = cnt + __popc(m & ((1u << lane) - 1u));
            if (hit && pos < S) outp[pos] = n;
            cnt += __popc(m);
        }
    }
    if (cnt > S) cnt = S;
    for (int s = cnt + lane; s < S; s += 32) outp[s] = first;
}

// ---------------- kernel 6: main fused GEMM + stats + max/min ----------------
__global__ __launch_bounds__(128)
void k_mlp(const float* __restrict__ bxyz) {
    __shared__ float g[CIN * SPITCH];   // 131*34*4 = 17816 B
    __shared__ int   sidx[S];
    __shared__ float scen[3];

    int q = blockIdx.x;                 // 0..NQ-1
    int b = q >> 11;
    int t = threadIdx.x;
    int w = t >> 5, lane = t & 31;

    if (t < S) sidx[t] = d_idx[(size_t)q * S + t];
    if (t < 3) scen[t] = d_newxyz[q * 3 + t];
    __syncthreads();

    const float* fb = d_featsT + (size_t)b * N * C;
    const float* xb = bxyz + (size_t)b * N * 3;

    // gather g: rows 0..2 = recentered xyz, rows 3..130 = features
    for (int s = w; s < S; s += 4) {
        int n = sidx[s];
        const float* fr = fb + (size_t)n * C;
#pragma unroll
        for (int j = 0; j < 4; j++) {
            int c = lane + 32 * j;
            g[(3 + c) * SPITCH + s] = fr[c];
        }
        if (lane < 3) g[lane * SPITCH + s] = xb[n * 3 + lane] - scen[lane];
    }
    __syncthreads();

    // compute y = Wt^T g : thread t owns output rows t and t+128
    u64 acc0[S / 2], acc1[S / 2];
    u64 z = pk2(0.0f);
#pragma unroll
    for (int j = 0; j < S / 2; j++) { acc0[j] = z; acc1[j] = z; }

    const float* wp0 = d_Wt + t;
    const float* wp1 = d_Wt + t + 128;
    for (int c = 0; c < CIN; c++) {
        u64 w0 = pk2(__ldg(wp0 + c * COUT));
        u64 w1 = pk2(__ldg(wp1 + c * COUT));
        const u64* gp = (const u64*)(g + c * SPITCH);   // 8B aligned (SPITCH even)
#pragma unroll
        for (int j = 0; j < S / 2; j++) {
            u64 gv = gp[j];
            acc0[j] = fma2(w0, gv, acc0[j]);
            acc1[j] = fma2(w1, gv, acc1[j]);
        }
    }

    // per-row reductions
#pragma unroll
    for (int r = 0; r < 2; r++) {
        u64* acc = (r == 0) ? acc0 : acc1;
        int o = t + r * 128;
        float mx = -INFINITY, mn = INFINITY, sm = 0.0f, sq = 0.0f;
#pragma unroll
        for (int j = 0; j < S / 2; j++) {
            float a, bv;
            upk2(acc[j], a, bv);
            mx = fmaxf(mx, fmaxf(a, bv));
            mn = fminf(mn, fminf(a, bv));
            sm += a + bv;
            sq += a * a + bv * bv;
        }
        d_mx[(size_t)q * COUT + o] = mx;
        d_mn[(size_t)q * COUT + o] = mn;
        atomicAdd(&d_sums[o],        (double)sm);
        atomicAdd(&d_sums[COUT + o], (double)sq);
    }
}

// ---------------- kernel 7: finalize (BN affine + ReLU + select max/min) ----------------
__global__ void k_finalize(const float* __restrict__ gamma,
                           const float* __restrict__ beta,
                           float* __restrict__ out) {
    int o = threadIdx.x;                        // channel (blockDim.x == COUT)
    size_t i = (size_t)blockIdx.x * COUT + o;   // element in (B,P,COUT)
    double m = d_sums[o] / MLPCNT;
    double v = d_sums[COUT + o] / MLPCNT - m * m;
    float a  = gamma[o] * rsqrtf((float)v + EPSB);
    float bb = beta[o] - (float)m * a;
    float val = (a >= 0.0f) ? d_mx[i] : d_mn[i];
    float r = a * val + bb;
    out[i] = fmaxf(r, 0.0f);
}

// ---------------- launch ----------------
extern "C" void kernel_launch(void* const* d_in, const int* in_sizes, int n_in,
                              void* d_out, int out_size) {
    const float* ffps   = (const float*)d_in[0];   // (B,P,3)
    const float* bxyz   = (const float*)d_in[1];   // (B,N,3)
    const float* feats  = (const float*)d_in[2];   // (B,C,N)
    const float* wsh    = (const float*)d_in[3];   // (3,3)
    const float* gsh    = (const float*)d_in[4];
    const float* bsh    = (const float*)d_in[5];
    const float* wmlp   = (const float*)d_in[6];   // (COUT, CIN)
    const float* gmlp   = (const float*)d_in[7];
    const float* bmlp   = (const float*)d_in[8];
    float* out = (float*)d_out;

    k_zero_stats<<<1, 512>>>();
    k_shift_stats<<<NQ / 256, 256>>>(ffps, wsh);
    k_shift_apply<<<NQ / 256, 256>>>(ffps, wsh, gsh, bsh);
    k_transpose_w<<<(COUT * CIN + 255) / 256, 256>>>(wmlp);
    k_transpose_f<<<dim3(N / 32, C / 32, B), dim3(32, 8)>>>(feats);
    k_ballquery<<<(NQ * 32) / 256, 256>>>(bxyz);
    k_mlp<<<NQ, 128>>>(bxyz);
    k_finalize<<<NQ, COUT>>>(gmlp, bmlp, out);
}

// round 5
// speedup vs baseline: 1.8758x; 1.8758x over previous
#include <cuda_runtime.h>
#include <cuda_fp16.h>
#include <cstdint>
#include <math.h>

// ---------------- problem constants ----------------
#define B     4
#define N     8192
#define P     2048
#define C     128
#define COUT  256
#define S     32
#define R2    0.64f
#define EPSB  1e-5f

#define NQ    (B*P)          // 8192 queries
#define NG2   (NQ/2)         // 4096 groups of 2 queries (64 samples)
#define MLPCNT ((double)(B)*(double)(P)*(double)(S))

// smem layout (bytes). Pitch 272 B (136 halves) -> conflict-free ldmatrix.
#define OFF_WHI 0            // W hi fp16 [256][136]   69632 B
#define OFF_WLO 69632        // W lo fp16 [256][136]   69632 B
#define OFF_G   139264       // 2 bufs x (Ghi[64][136] + Glo[64][136]) = 2 x 34816
#define GBUF    34816
#define GLOOFF  17408
#define OFF_GX  208896       // 2 bufs x 64 samples x 16 B (recentered xyz fp32)
#define SMEM_TOTAL 210944

// ---------------- device scratch ----------------
__device__ float          d_newxyz[NQ * 3];
__device__ int            d_idx[NQ * S];
__device__ unsigned short d_fhi[(size_t)B * N * C];   // fp16 hi of featsT (B,N,C)
__device__ unsigned short d_flo[(size_t)B * N * C];   // fp16 lo residual
__device__ float          d_mx[NQ * COUT];
__device__ float          d_mn[NQ * COUT];
__device__ double         d_sums[2 * COUT];
__device__ double         d_sst[6];

// ---------------- PTX helpers ----------------
__device__ __forceinline__ uint32_t smem_u32(const void* p) {
    uint32_t a;
    asm("{ .reg .u64 t; cvta.to.shared.u64 t, %1; cvt.u32.u64 %0, t; }" : "=r"(a) : "l"(p));
    return a;
}
__device__ __forceinline__ void ldsm4(uint32_t* r, uint32_t addr) {
    asm volatile("ldmatrix.sync.aligned.m8n8.x4.shared.b16 {%0,%1,%2,%3}, [%4];"
                 : "=r"(r[0]), "=r"(r[1]), "=r"(r[2]), "=r"(r[3]) : "r"(addr));
}
__device__ __forceinline__ void mma16816(float* d, const uint32_t* a, const uint32_t* b) {
    asm volatile("mma.sync.aligned.m16n8k16.row.col.f32.f16.f16.f32 "
                 "{%0,%1,%2,%3}, {%4,%5,%6,%7}, {%8,%9}, {%0,%1,%2,%3};"
                 : "+f"(d[0]), "+f"(d[1]), "+f"(d[2]), "+f"(d[3])
                 : "r"(a[0]), "r"(a[1]), "r"(a[2]), "r"(a[3]), "r"(b[0]), "r"(b[1]));
}

// ---------------- kernel 0: zero stats ----------------
__global__ void k_zero_stats() {
    int t = threadIdx.x;
    if (t < 2 * COUT) d_sums[t] = 0.0;
    if (t < 6)        d_sst[t]  = 0.0;
}

// ---------------- kernel 1: shift GEMM + BN stats ----------------
__global__ void k_shift_stats(const float* __restrict__ ffps,
                              const float* __restrict__ wsh) {
    int i = blockIdx.x * blockDim.x + threadIdx.x;
    float f0 = ffps[i*3+0], f1 = ffps[i*3+1], f2 = ffps[i*3+2];
    float xs[3], xq[3];
#pragma unroll
    for (int o = 0; o < 3; o++) {
        float x = wsh[o*3+0]*f0 + wsh[o*3+1]*f1 + wsh[o*3+2]*f2;
        xs[o] = x; xq[o] = x * x;
    }
#pragma unroll
    for (int off = 16; off > 0; off >>= 1) {
#pragma unroll
        for (int o = 0; o < 3; o++) {
            xs[o] += __shfl_down_sync(0xffffffffu, xs[o], off);
            xq[o] += __shfl_down_sync(0xffffffffu, xq[o], off);
        }
    }
    if ((threadIdx.x & 31) == 0) {
#pragma unroll
        for (int o = 0; o < 3; o++) {
            atomicAdd(&d_sst[o],   (double)xs[o]);
            atomicAdd(&d_sst[3+o], (double)xq[o]);
        }
    }
}

// ---------------- kernel 2: apply shift BN + ReLU ----------------
__global__ void k_shift_apply(const float* __restrict__ ffps,
                              const float* __restrict__ wsh,
                              const float* __restrict__ gamma,
                              const float* __restrict__ beta) {
    int i = blockIdx.x * blockDim.x + threadIdx.x;
    float f0 = ffps[i*3+0], f1 = ffps[i*3+1], f2 = ffps[i*3+2];
#pragma unroll
    for (int o = 0; o < 3; o++) {
        float x = wsh[o*3+0]*f0 + wsh[o*3+1]*f1 + wsh[o*3+2]*f2;
        double cnt = (double)NQ;
        double m = d_sst[o] / cnt;
        double v = d_sst[3+o] / cnt - m * m;
        float a = gamma[o] * rsqrtf((float)v + EPSB);
        float val = (x - (float)m) * a + beta[o];
        d_newxyz[i*3+o] = fmaxf(val, 0.0f);
    }
}

// ---------------- kernel 3: transpose + fp16 hi/lo split ----------------
__global__ void k_transpose_f(const float* __restrict__ f) {
    __shared__ float tile[32][33];
    int b  = blockIdx.z;
    int n0 = blockIdx.x * 32;
    int c0 = blockIdx.y * 32;
    const float* src = f + ((size_t)b * C + c0) * N + n0;
#pragma unroll
    for (int r = threadIdx.y; r < 32; r += 8)
        tile[r][threadIdx.x] = src[(size_t)r * N + threadIdx.x];
    __syncthreads();
    size_t base = ((size_t)b * N + n0) * C + c0;
#pragma unroll
    for (int r = threadIdx.y; r < 32; r += 8) {
        float v = tile[threadIdx.x][r];
        __half h = __float2half_rn(v);
        __half l = __float2half_rn(v - __half2float(h));
        size_t o = base + (size_t)r * C + threadIdx.x;
        d_fhi[o] = __half_as_ushort(h);
        d_flo[o] = __half_as_ushort(l);
    }
}

// ---------------- kernel 4: ball query (warp per query) ----------------
__global__ void k_ballquery(const float* __restrict__ bxyz) {
    int wid  = (blockIdx.x * blockDim.x + threadIdx.x) >> 5;
    int lane = threadIdx.x & 31;
    if (wid >= NQ) return;
    int b = wid >> 11;
    float cx = d_newxyz[wid*3+0];
    float cy = d_newxyz[wid*3+1];
    float cz = d_newxyz[wid*3+2];
    const float* xb = bxyz + (size_t)b * N * 3;
    int* outp = d_idx + (size_t)wid * S;

    int cnt = 0, first = 0;
    bool found = false;
    for (int n0 = 0; n0 < N && cnt < S; n0 += 32) {
        int n = n0 + lane;
        float dx = xb[n*3+0] - cx;
        float dy = xb[n*3+1] - cy;
        float dz = xb[n*3+2] - cz;
        float d2 = dx*dx + dy*dy + dz*dz;
        unsigned m = __ballot_sync(0xffffffffu, d2 < R2);
        if (m) {
            if (!found) { found = true; first = n0 + __ffs(m) - 1; }
            bool hit = (m >> lane) & 1u;
            int pos = cnt + __popc(m & ((1u << lane) - 1u));
            if (hit && pos < S) outp[pos] = n;
            cnt += __popc(m);
        }
    }
    if (cnt > S) cnt = S;
    for (int s = cnt + lane; s < S; s += 32) outp[s] = first;
}

// ---------------- kernel 5: persistent HMMA MLP ----------------
// D[256 x 64] = W[256 x 128] * G^T, 3-pass fp16 hi/lo split, xyz folded into epilogue.
__global__ __launch_bounds__(256, 1)
void k_mlp(const float* __restrict__ bxyz, const float* __restrict__ wmlp) {
    extern __shared__ char smc[];
    uint32_t smb = smem_u32(smc);
    int t = threadIdx.x;
    int warp = t >> 5, lane = t & 31;

    // ---- W -> smem fp16 hi/lo (one time) ----
    for (int idx = t; idx < 256 * 128; idx += 256) {
        int o = idx >> 7, k = idx & 127;
        float v = wmlp[o * 131 + 3 + k];
        __half h = __float2half_rn(v);
        __half l = __float2half_rn(v - __half2float(h));
        *(__half*)(smc + OFF_WHI + o * 272 + k * 2) = h;
        *(__half*)(smc + OFF_WLO + o * 272 + k * 2) = l;
    }

    // ---- per-thread xyz weights (rows fixed per thread) ----
    float wx[4][3];
#pragma unroll
    for (int k = 0; k < 4; k++) {
        int o = warp * 32 + 16 * (k >> 1) + (lane >> 2) + 8 * (k & 1);
#pragma unroll
        for (int j = 0; j < 3; j++) wx[k][j] = wmlp[o * 131 + j];
    }

    // ---- ldmatrix per-thread address components ----
    int sub = lane & 7, grp = lane >> 3;
    int rowA = sub + 8 * (grp & 1);  uint32_t kA2 = (uint32_t)(grp >> 1) * 16;
    int rowB = sub + 8 * (grp >> 1); uint32_t kB2 = (uint32_t)(grp & 1) * 16;
    uint32_t aHi0 = smb + OFF_WHI + (uint32_t)(warp * 32 + rowA) * 272 + kA2;
    uint32_t aHi1 = aHi0 + 16 * 272;
    uint32_t aLo0 = aHi0 + (OFF_WLO - OFF_WHI);
    uint32_t aLo1 = aHi1 + (OFF_WLO - OFF_WHI);
    uint32_t bRow = (uint32_t)rowB * 272 + kB2;

    // ---- prologue: gather group blockIdx.x into buffer 0 ----
    {
        int g = blockIdx.x;
        const int* idxp = d_idx + (size_t)g * 64;
        int bb = g >> 10;
        int l16 = lane & 15, hh = lane >> 4;
#pragma unroll
        for (int j = 0; j < 4; j++) {
            int s = warp * 8 + 2 * j + hh;
            int n = idxp[s];
            size_t rowo = ((size_t)bb * N + n) * C;
            uint4 uh = ((const uint4*)(d_fhi + rowo))[l16];
            uint4 ul = ((const uint4*)(d_flo + rowo))[l16];
            *(uint4*)(smc + OFF_G + s * 272 + l16 * 16) = uh;
            *(uint4*)(smc + OFF_G + GLOOFF + s * 272 + l16 * 16) = ul;
        }
        if (lane < 8) {
            int s = warp * 8 + lane;
            int n = idxp[s];
            int q = g * 2 + (s >> 5);
            const float* cen = d_newxyz + (size_t)q * 3;
            const float* xp  = bxyz + ((size_t)bb * N + n) * 3;
            float* gp = (float*)(smc + OFF_GX + s * 16);
            gp[0] = xp[0] - cen[0];
            gp[1] = xp[1] - cen[1];
            gp[2] = xp[2] - cen[2];
        }
    }
    __syncthreads();

    float sums[4] = {0.f, 0.f, 0.f, 0.f}, sqs[4] = {0.f, 0.f, 0.f, 0.f};
    int it = 0;
    for (int g = blockIdx.x; g < NG2; g += gridDim.x, it++) {
        int p = it & 1;

        // ---- issue next group's gather LDGs (complete during MMA) ----
        int gn = g + gridDim.x;
        bool have = gn < NG2;
        uint4 gh[4], gl[4];
        float px0 = 0, px1 = 0, px2 = 0, c0 = 0, c1 = 0, c2 = 0;
        if (have) {
            const int* idxp = d_idx + (size_t)gn * 64;
            int bb = gn >> 10;
            int l16 = lane & 15, hh = lane >> 4;
#pragma unroll
            for (int j = 0; j < 4; j++) {
                int s = warp * 8 + 2 * j + hh;
                int n = idxp[s];
                size_t rowo = ((size_t)bb * N + n) * C;
                gh[j] = ((const uint4*)(d_fhi + rowo))[l16];
                gl[j] = ((const uint4*)(d_flo + rowo))[l16];
            }
            if (lane < 8) {
                int s = warp * 8 + lane;
                int n = idxp[s];
                int q = gn * 2 + (s >> 5);
                px0 = bxyz[((size_t)bb * N + n) * 3 + 0];
                px1 = bxyz[((size_t)bb * N + n) * 3 + 1];
                px2 = bxyz[((size_t)bb * N + n) * 3 + 2];
                c0 = d_newxyz[(size_t)q * 3 + 0];
                c1 = d_newxyz[(size_t)q * 3 + 1];
                c2 = d_newxyz[(size_t)q * 3 + 2];
            }
        }

        // ---- 3-pass MMA: Whi*Ghi + Whi*Glo + Wlo*Ghi ----
        float acc[2][32];
#pragma unroll
        for (int m = 0; m < 2; m++)
#pragma unroll
            for (int j = 0; j < 32; j++) acc[m][j] = 0.f;

        uint32_t bBase = smb + OFF_G + (uint32_t)p * GBUF + bRow;
#pragma unroll
        for (int ks = 0; ks < 8; ks++) {
            uint32_t kb = (uint32_t)ks * 32;
            uint32_t ah0[4], ah1[4], al0[4], al1[4], bh[16], bl[16];
            ldsm4(ah0, aHi0 + kb);
            ldsm4(ah1, aHi1 + kb);
            ldsm4(al0, aLo0 + kb);
            ldsm4(al1, aLo1 + kb);
#pragma unroll
            for (int a = 0; a < 4; a++) {
                ldsm4(&bh[4 * a], bBase + (uint32_t)a * 16 * 272 + kb);
                ldsm4(&bl[4 * a], bBase + GLOOFF + (uint32_t)a * 16 * 272 + kb);
            }
#pragma unroll
            for (int m = 0; m < 2; m++) {
                uint32_t* ah = m ? ah1 : ah0;
                uint32_t* al = m ? al1 : al0;
#pragma unroll
                for (int n = 0; n < 8; n++) {
                    int bi = (n >> 1) * 4 + (n & 1) * 2;
                    mma16816(&acc[m][4 * n], ah, &bh[bi]);
                    mma16816(&acc[m][4 * n], ah, &bl[bi]);
                    mma16816(&acc[m][4 * n], al, &bh[bi]);
                }
            }
        }

        // ---- store gathered data into the other buffer ----
        if (have) {
            int pn = p ^ 1;
            int l16 = lane & 15, hh = lane >> 4;
#pragma unroll
            for (int j = 0; j < 4; j++) {
                int s = warp * 8 + 2 * j + hh;
                *(uint4*)(smc + OFF_G + pn * GBUF + s * 272 + l16 * 16) = gh[j];
                *(uint4*)(smc + OFF_G + pn * GBUF + GLOOFF + s * 272 + l16 * 16) = gl[j];
            }
            if (lane < 8) {
                int s = warp * 8 + lane;
                float* gp = (float*)(smc + OFF_GX + pn * 1024 + s * 16);
                gp[0] = px0 - c0; gp[1] = px1 - c1; gp[2] = px2 - c2;
            }
        }

        // ---- epilogue: xyz FMA + max/min + running sums ----
        float mxq[4][2], mnq[4][2];
#pragma unroll
        for (int k = 0; k < 4; k++)
#pragma unroll
            for (int q = 0; q < 2; q++) { mxq[k][q] = -INFINITY; mnq[k][q] = INFINITY; }

#pragma unroll
        for (int c = 0; c < 16; c++) {
            int na = c >> 1, e = c & 1;
            int col = na * 8 + 2 * (lane & 3) + e;
            const float* gp = (const float*)(smc + OFF_GX + p * 1024 + col * 16);
            float g0 = gp[0], g1 = gp[1], g2 = gp[2];
            int q = na >> 2;
#pragma unroll
            for (int k = 0; k < 4; k++) {
                int m = k >> 1, ds = k & 1;
                float v = acc[m][na * 4 + ds * 2 + e]
                        + wx[k][0] * g0 + wx[k][1] * g1 + wx[k][2] * g2;
                mxq[k][q] = fmaxf(mxq[k][q], v);
                mnq[k][q] = fminf(mnq[k][q], v);
                sums[k] += v; sqs[k] += v * v;
            }
        }
#pragma unroll
        for (int k = 0; k < 4; k++) {
#pragma unroll
            for (int q = 0; q < 2; q++) {
                float mx = mxq[k][q], mn = mnq[k][q];
                mx = fmaxf(mx, __shfl_xor_sync(0xffffffffu, mx, 1));
                mx = fmaxf(mx, __shfl_xor_sync(0xffffffffu, mx, 2));
                mn = fminf(mn, __shfl_xor_sync(0xffffffffu, mn, 1));
                mn = fminf(mn, __shfl_xor_sync(0xffffffffu, mn, 2));
                if ((lane & 3) == 0) {
                    int o = warp * 32 + 16 * (k >> 1) + (lane >> 2) + 8 * (k & 1);
                    size_t qg = (size_t)(g * 2 + q);
                    d_mx[qg * COUT + o] = mx;
                    d_mn[qg * COUT + o] = mn;
                }
            }
        }
        __syncthreads();
    }

    // ---- flush channel sums ----
#pragma unroll
    for (int k = 0; k < 4; k++) {
        float s_ = sums[k], q_ = sqs[k];
        s_ += __shfl_xor_sync(0xffffffffu, s_, 1);
        s_ += __shfl_xor_sync(0xffffffffu, s_, 2);
        q_ += __shfl_xor_sync(0xffffffffu, q_, 1);
        q_ += __shfl_xor_sync(0xffffffffu, q_, 2);
        if ((lane & 3) == 0) {
            int o = warp * 32 + 16 * (k >> 1) + (lane >> 2) + 8 * (k & 1);
            atomicAdd(&d_sums[o],        (double)s_);
            atomicAdd(&d_sums[COUT + o], (double)q_);
        }
    }
}

// ---------------- kernel 6: finalize ----------------
__global__ void k_finalize(const float* __restrict__ gamma,
                           const float* __restrict__ beta,
                           float* __restrict__ out) {
    int o = threadIdx.x;
    size_t i = (size_t)blockIdx.x * COUT + o;
    double m = d_sums[o] / MLPCNT;
    double v = d_sums[COUT + o] / MLPCNT - m * m;
    float a  = gamma[o] * rsqrtf((float)v + EPSB);
    float bb = beta[o] - (float)m * a;
    float val = (a >= 0.0f) ? d_mx[i] : d_mn[i];
    out[i] = fmaxf(a * val + bb, 0.0f);
}

// ---------------- launch ----------------
extern "C" void kernel_launch(void* const* d_in, const int* in_sizes, int n_in,
                              void* d_out, int out_size) {
    const float* ffps  = (const float*)d_in[0];
    const float* bxyz  = (const float*)d_in[1];
    const float* feats = (const float*)d_in[2];
    const float* wsh   = (const float*)d_in[3];
    const float* gsh   = (const float*)d_in[4];
    const float* bsh   = (const float*)d_in[5];
    const float* wmlp  = (const float*)d_in[6];
    const float* gmlp  = (const float*)d_in[7];
    const float* bmlp  = (const float*)d_in[8];
    float* out = (float*)d_out;

    cudaFuncSetAttribute(k_mlp, cudaFuncAttributeMaxDynamicSharedMemorySize, SMEM_TOTAL);

    k_zero_stats<<<1, 512>>>();
    k_shift_stats<<<NQ / 256, 256>>>(ffps, wsh);
    k_shift_apply<<<NQ / 256, 256>>>(ffps, wsh, gsh, bsh);
    k_transpose_f<<<dim3(N / 32, C / 32, B), dim3(32, 8)>>>(feats);
    k_ballquery<<<(NQ * 32) / 256, 256>>>(bxyz);
    k_mlp<<<152, 256, SMEM_TOTAL>>>(bxyz, wmlp);
    k_finalize<<<NQ, COUT>>>(gmlp, bmlp, out);
}

// round 6
// speedup vs baseline: 2.1775x; 1.1608x over previous
#include <cuda_runtime.h>
#include <cuda_fp16.h>
#include <cstdint>
#include <math.h>

// ---------------- problem constants ----------------
#define B     4
#define N     8192
#define P     2048
#define C     128
#define COUT  256
#define S     32
#define R2    0.64f
#define EPSB  1e-5f

#define NQ    (B*P)          // 8192 queries
#define NG2   (NQ/2)         // 4096 groups of 2 queries (64 samples)
#define MLPCNT ((double)(B)*(double)(P)*(double)(S))

// smem layout (bytes). Pitch 272 B (136 halves) -> conflict-free ldmatrix.
#define OFF_WHI 0            // W hi fp16 [256][136]   69632 B
#define OFF_WLO 69632        // W lo fp16 [256][136]   69632 B
#define OFF_G   139264       // 2 bufs x Ghi[64][136] = 2 x 17408
#define GBUF    17408
#define OFF_GX  174080       // 2 bufs x 64 samples x 16 B (recentered xyz fp32)
#define SMEM_TOTAL 176128

// ---------------- device scratch ----------------
__device__ float          d_newxyz[NQ * 3];
__device__ int            d_idx[NQ * S];
__device__ unsigned short d_fhi[(size_t)B * N * C];   // fp16 of featsT (B,N,C)
__device__ float          d_mx[NQ * COUT];
__device__ float          d_mn[NQ * COUT];
__device__ double         d_sums[2 * COUT];
__device__ double         d_sst[6];

// ---------------- PTX helpers ----------------
__device__ __forceinline__ uint32_t smem_u32(const void* p) {
    uint32_t a;
    asm("{ .reg .u64 t; cvta.to.shared.u64 t, %1; cvt.u32.u64 %0, t; }" : "=r"(a) : "l"(p));
    return a;
}
__device__ __forceinline__ void ldsm4(uint32_t* r, uint32_t addr) {
    asm volatile("ldmatrix.sync.aligned.m8n8.x4.shared.b16 {%0,%1,%2,%3}, [%4];"
                 : "=r"(r[0]), "=r"(r[1]), "=r"(r[2]), "=r"(r[3]) : "r"(addr));
}
__device__ __forceinline__ void mma16816(float* d, const uint32_t* a, const uint32_t* b) {
    asm volatile("mma.sync.aligned.m16n8k16.row.col.f32.f16.f16.f32 "
                 "{%0,%1,%2,%3}, {%4,%5,%6,%7}, {%8,%9}, {%0,%1,%2,%3};"
                 : "+f"(d[0]), "+f"(d[1]), "+f"(d[2]), "+f"(d[3])
                 : "r"(a[0]), "r"(a[1]), "r"(a[2]), "r"(a[3]), "r"(b[0]), "r"(b[1]));
}

// ---------------- kernel 0: zero stats ----------------
__global__ void k_zero_stats() {
    int t = threadIdx.x;
    if (t < 2 * COUT) d_sums[t] = 0.0;
    if (t < 6)        d_sst[t]  = 0.0;
}

// ---------------- kernel 1: shift GEMM + BN stats ----------------
__global__ void k_shift_stats(const float* __restrict__ ffps,
                              const float* __restrict__ wsh) {
    int i = blockIdx.x * blockDim.x + threadIdx.x;
    float f0 = ffps[i*3+0], f1 = ffps[i*3+1], f2 = ffps[i*3+2];
    float xs[3], xq[3];
#pragma unroll
    for (int o = 0; o < 3; o++) {
        float x = wsh[o*3+0]*f0 + wsh[o*3+1]*f1 + wsh[o*3+2]*f2;
        xs[o] = x; xq[o] = x * x;
    }
#pragma unroll
    for (int off = 16; off > 0; off >>= 1) {
#pragma unroll
        for (int o = 0; o < 3; o++) {
            xs[o] += __shfl_down_sync(0xffffffffu, xs[o], off);
            xq[o] += __shfl_down_sync(0xffffffffu, xq[o], off);
        }
    }
    if ((threadIdx.x & 31) == 0) {
#pragma unroll
        for (int o = 0; o < 3; o++) {
            atomicAdd(&d_sst[o],   (double)xs[o]);
            atomicAdd(&d_sst[3+o], (double)xq[o]);
        }
    }
}

// ---------------- kernel 2: fused prep (feature transpose + shift-apply + ball query) ----
// blocks [0, 4096): transpose (B,C,N)->fp16 (B,N,C)
// blocks [4096, 5120): ball query, 8 warps = 8 queries per block, center computed inline
__global__ void k_prep(const float* __restrict__ f,
                       const float* __restrict__ bxyz,
                       const float* __restrict__ ffps,
                       const float* __restrict__ wsh,
                       const float* __restrict__ gamma,
                       const float* __restrict__ beta) {
    if (blockIdx.x < 4096) {
        // ---------- transpose part ----------
        __shared__ float tile[32][33];
        int bid = blockIdx.x;
        int tx = threadIdx.x & 31, ty = threadIdx.x >> 5;   // (32, 8)
        int b  = bid >> 10;
        int c0 = (bid >> 8) & 3;  c0 *= 32;
        int n0 = (bid & 255) * 32;
        const float* src = f + ((size_t)b * C + c0) * N + n0;
#pragma unroll
        for (int r = ty; r < 32; r += 8)
            tile[r][tx] = src[(size_t)r * N + tx];
        __syncthreads();
        size_t base = ((size_t)b * N + n0) * C + c0;
#pragma unroll
        for (int r = ty; r < 32; r += 8)
            d_fhi[base + (size_t)r * C + tx] =
                __half_as_ushort(__float2half_rn(tile[tx][r]));
        return;
    }

    // ---------- ball query part ----------
    int wid  = (blockIdx.x - 4096) * 8 + (threadIdx.x >> 5);   // query id
    int lane = threadIdx.x & 31;
    int b = wid >> 11;

    // compute this query's center (shift GEMM + BN + ReLU), all lanes redundantly
    float cen[3];
    {
        const float* fp = ffps + (size_t)wid * 3;
        float f0 = fp[0], f1 = fp[1], f2 = fp[2];
        double cnt = (double)NQ;
#pragma unroll
        for (int o = 0; o < 3; o++) {
            float x = wsh[o*3+0]*f0 + wsh[o*3+1]*f1 + wsh[o*3+2]*f2;
            double m = d_sst[o] / cnt;
            double v = d_sst[3+o] / cnt - m * m;
            float a = gamma[o] * rsqrtf((float)v + EPSB);
            cen[o] = fmaxf((x - (float)m) * a + beta[o], 0.0f);
        }
    }
    if (lane == 0) {
        d_newxyz[wid*3+0] = cen[0];
        d_newxyz[wid*3+1] = cen[1];
        d_newxyz[wid*3+2] = cen[2];
    }

    int* outp = d_idx + (size_t)wid * S;

    // empty-ball skip: points lie in [-1,1); any center coord >= 1.8 -> no hits
    if (cen[0] >= 1.8f || cen[1] >= 1.8f || cen[2] >= 1.8f) {
        if (lane < S) outp[lane] = 0;
        return;
    }

    const float* xb = bxyz + (size_t)b * N * 3;
    int cnt = 0, first = 0;
    bool found = false;
    for (int n0 = 0; n0 < N && cnt < S; n0 += 32) {
        int n = n0 + lane;
        float dx = xb[n*3+0] - cen[0];
        float dy = xb[n*3+1] - cen[1];
        float dz = xb[n*3+2] - cen[2];
        float d2 = dx*dx + dy*dy + dz*dz;
        unsigned m = __ballot_sync(0xffffffffu, d2 < R2);
        if (m) {
            if (!found) { found = true; first = n0 + __ffs(m) - 1; }
            bool hit = (m >> lane) & 1u;
            int pos = cnt + __popc(m & ((1u << lane) - 1u));
            if (hit && pos < S) outp[pos] = n;
            cnt += __popc(m);
        }
    }
    if (cnt > S) cnt = S;
    for (int s = cnt + lane; s < S; s += 32) outp[s] = first;
}

// ---------------- kernel 3: persistent HMMA MLP ----------------
// D[256 x 64] = W[256 x 128] * G^T, 2-pass fp16 split (Whi*Ghi + Wlo*Ghi),
// xyz channels folded into the fp32 epilogue.
__global__ __launch_bounds__(256, 1)
void k_mlp(const float* __restrict__ bxyz, const float* __restrict__ wmlp) {
    extern __shared__ char smc[];
    uint32_t smb = smem_u32(smc);
    int t = threadIdx.x;
    int warp = t >> 5, lane = t & 31;

    // ---- W -> smem fp16 hi/lo (one time) ----
    for (int idx = t; idx < 256 * 128; idx += 256) {
        int o = idx >> 7, k = idx & 127;
        float v = wmlp[o * 131 + 3 + k];
        __half h = __float2half_rn(v);
        __half l = __float2half_rn(v - __half2float(h));
        *(__half*)(smc + OFF_WHI + o * 272 + k * 2) = h;
        *(__half*)(smc + OFF_WLO + o * 272 + k * 2) = l;
    }

    // ---- per-thread xyz weights (rows fixed per thread) ----
    float wx[4][3];
#pragma unroll
    for (int k = 0; k < 4; k++) {
        int o = warp * 32 + 16 * (k >> 1) + (lane >> 2) + 8 * (k & 1);
#pragma unroll
        for (int j = 0; j < 3; j++) wx[k][j] = wmlp[o * 131 + j];
    }

    // ---- ldmatrix per-thread address components ----
    int sub = lane & 7, grp = lane >> 3;
    int rowA = sub + 8 * (grp & 1);  uint32_t kA2 = (uint32_t)(grp >> 1) * 16;
    int rowB = sub + 8 * (grp >> 1); uint32_t kB2 = (uint32_t)(grp & 1) * 16;
    uint32_t aHi0 = smb + OFF_WHI + (uint32_t)(warp * 32 + rowA) * 272 + kA2;
    uint32_t aHi1 = aHi0 + 16 * 272;
    uint32_t aLo0 = aHi0 + (OFF_WLO - OFF_WHI);
    uint32_t aLo1 = aHi1 + (OFF_WLO - OFF_WHI);
    uint32_t bRow = (uint32_t)rowB * 272 + kB2;

    // ---- prologue: gather group blockIdx.x into buffer 0 ----
    {
        int g = blockIdx.x;
        const int* idxp = d_idx + (size_t)g * 64;
        int bb = g >> 10;
        int l16 = lane & 15, hh = lane >> 4;
#pragma unroll
        for (int j = 0; j < 4; j++) {
            int s = warp * 8 + 2 * j + hh;
            int n = idxp[s];
            size_t rowo = ((size_t)bb * N + n) * C;
            uint4 uh = ((const uint4*)(d_fhi + rowo))[l16];
            *(uint4*)(smc + OFF_G + s * 272 + l16 * 16) = uh;
        }
        if (lane < 8) {
            int s = warp * 8 + lane;
            int n = idxp[s];
            int q = g * 2 + (s >> 5);
            const float* cen = d_newxyz + (size_t)q * 3;
            const float* xp  = bxyz + ((size_t)bb * N + n) * 3;
            float* gp = (float*)(smc + OFF_GX + s * 16);
            gp[0] = xp[0] - cen[0];
            gp[1] = xp[1] - cen[1];
            gp[2] = xp[2] - cen[2];
        }
    }
    __syncthreads();

    float sums[4] = {0.f, 0.f, 0.f, 0.f}, sqs[4] = {0.f, 0.f, 0.f, 0.f};
    int it = 0;
    for (int g = blockIdx.x; g < NG2; g += gridDim.x, it++) {
        int p = it & 1;

        // ---- issue next group's gather LDGs (complete during MMA) ----
        int gn = g + gridDim.x;
        bool have = gn < NG2;
        uint4 gh[4];
        float px0 = 0, px1 = 0, px2 = 0, c0 = 0, c1 = 0, c2 = 0;
        if (have) {
            const int* idxp = d_idx + (size_t)gn * 64;
            int bb = gn >> 10;
            int l16 = lane & 15, hh = lane >> 4;
#pragma unroll
            for (int j = 0; j < 4; j++) {
                int s = warp * 8 + 2 * j + hh;
                int n = idxp[s];
                size_t rowo = ((size_t)bb * N + n) * C;
                gh[j] = ((const uint4*)(d_fhi + rowo))[l16];
            }
            if (lane < 8) {
                int s = warp * 8 + lane;
                int n = idxp[s];
                int q = gn * 2 + (s >> 5);
                px0 = bxyz[((size_t)bb * N + n) * 3 + 0];
                px1 = bxyz[((size_t)bb * N + n) * 3 + 1];
                px2 = bxyz[((size_t)bb * N + n) * 3 + 2];
                c0 = d_newxyz[(size_t)q * 3 + 0];
                c1 = d_newxyz[(size_t)q * 3 + 1];
                c2 = d_newxyz[(size_t)q * 3 + 2];
            }
        }

        // ---- 2-pass MMA: Whi*Ghi + Wlo*Ghi (shared B fragments) ----
        float acc[2][32];
#pragma unroll
        for (int m = 0; m < 2; m++)
#pragma unroll
            for (int j = 0; j < 32; j++) acc[m][j] = 0.f;

        uint32_t bBase = smb + OFF_G + (uint32_t)p * GBUF + bRow;
#pragma unroll
        for (int ks = 0; ks < 8; ks++) {
            uint32_t kb = (uint32_t)ks * 32;
            uint32_t ah0[4], ah1[4], al0[4], al1[4], bh[16];
            ldsm4(ah0, aHi0 + kb);
            ldsm4(ah1, aHi1 + kb);
            ldsm4(al0, aLo0 + kb);
            ldsm4(al1, aLo1 + kb);
#pragma unroll
            for (int a = 0; a < 4; a++)
                ldsm4(&bh[4 * a], bBase + (uint32_t)a * 16 * 272 + kb);
#pragma unroll
            for (int m = 0; m < 2; m++) {
                uint32_t* ah = m ? ah1 : ah0;
                uint32_t* al = m ? al1 : al0;
#pragma unroll
                for (int n = 0; n < 8; n++) {
                    int bi = (n >> 1) * 4 + (n & 1) * 2;
                    mma16816(&acc[m][4 * n], ah, &bh[bi]);
                    mma16816(&acc[m][4 * n], al, &bh[bi]);
                }
            }
        }

        // ---- store gathered data into the other buffer ----
        if (have) {
            int pn = p ^ 1;
            int l16 = lane & 15, hh = lane >> 4;
#pragma unroll
            for (int j = 0; j < 4; j++) {
                int s = warp * 8 + 2 * j + hh;
                *(uint4*)(smc + OFF_G + pn * GBUF + s * 272 + l16 * 16) = gh[j];
            }
            if (lane < 8) {
                int s = warp * 8 + lane;
                float* gp = (float*)(smc + OFF_GX + pn * 1024 + s * 16);
                gp[0] = px0 - c0; gp[1] = px1 - c1; gp[2] = px2 - c2;
            }
        }

        // ---- epilogue: xyz FMA + max/min + running sums ----
        float mxq[4][2], mnq[4][2];
#pragma unroll
        for (int k = 0; k < 4; k++)
#pragma unroll
            for (int q = 0; q < 2; q++) { mxq[k][q] = -INFINITY; mnq[k][q] = INFINITY; }

#pragma unroll
        for (int c = 0; c < 16; c++) {
            int na = c >> 1, e = c & 1;
            int col = na * 8 + 2 * (lane & 3) + e;
            const float* gp = (const float*)(smc + OFF_GX + p * 1024 + col * 16);
            float g0 = gp[0], g1 = gp[1], g2 = gp[2];
            int q = na >> 2;
#pragma unroll
            for (int k = 0; k < 4; k++) {
                int m = k >> 1, ds = k & 1;
                float v = acc[m][na * 4 + ds * 2 + e]
                        + wx[k][0] * g0 + wx[k][1] * g1 + wx[k][2] * g2;
                mxq[k][q] = fmaxf(mxq[k][q], v);
                mnq[k][q] = fminf(mnq[k][q], v);
                sums[k] += v; sqs[k] += v * v;
            }
        }
#pragma unroll
        for (int k = 0; k < 4; k++) {
#pragma unroll
            for (int q = 0; q < 2; q++) {
                float mx = mxq[k][q], mn = mnq[k][q];
                mx = fmaxf(mx, __shfl_xor_sync(0xffffffffu, mx, 1));
                mx = fmaxf(mx, __shfl_xor_sync(0xffffffffu, mx, 2));
                mn = fminf(mn, __shfl_xor_sync(0xffffffffu, mn, 1));
                mn = fminf(mn, __shfl_xor_sync(0xffffffffu, mn, 2));
                if ((lane & 3) == 0) {
                    int o = warp * 32 + 16 * (k >> 1) + (lane >> 2) + 8 * (k & 1);
                    size_t qg = (size_t)(g * 2 + q);
                    d_mx[qg * COUT + o] = mx;
                    d_mn[qg * COUT + o] = mn;
                }
            }
        }
        __syncthreads();
    }

    // ---- flush channel sums ----
#pragma unroll
    for (int k = 0; k < 4; k++) {
        float s_ = sums[k], q_ = sqs[k];
        s_ += __shfl_xor_sync(0xffffffffu, s_, 1);
        s_ += __shfl_xor_sync(0xffffffffu, s_, 2);
        q_ += __shfl_xor_sync(0xffffffffu, q_, 1);
        q_ += __shfl_xor_sync(0xffffffffu, q_, 2);
        if ((lane & 3) == 0) {
            int o = warp * 32 + 16 * (k >> 1) + (lane >> 2) + 8 * (k & 1);
            atomicAdd(&d_sums[o],        (double)s_);
            atomicAdd(&d_sums[COUT + o], (double)q_);
        }
    }
}

// ---------------- kernel 4: finalize ----------------
__global__ void k_finalize(const float* __restrict__ gamma,
                           const float* __restrict__ beta,
                           float* __restrict__ out) {
    int o = threadIdx.x;
    size_t i = (size_t)blockIdx.x * COUT + o;
    double m = d_sums[o] / MLPCNT;
    double v = d_sums[COUT + o] / MLPCNT - m * m;
    float a  = gamma[o] * rsqrtf((float)v + EPSB);
    float bb = beta[o] - (float)m * a;
    const float* src = (a >= 0.0f) ? d_mx : d_mn;   // load only the needed array
    out[i] = fmaxf(a * src[i] + bb, 0.0f);
}

// ---------------- launch ----------------
extern "C" void kernel_launch(void* const* d_in, const int* in_sizes, int n_in,
                              void* d_out, int out_size) {
    const float* ffps  = (const float*)d_in[0];
    const float* bxyz  = (const float*)d_in[1];
    const float* feats = (const float*)d_in[2];
    const float* wsh   = (const float*)d_in[3];
    const float* gsh   = (const float*)d_in[4];
    const float* bsh   = (const float*)d_in[5];
    const float* wmlp  = (const float*)d_in[6];
    const float* gmlp  = (const float*)d_in[7];
    const float* bmlp  = (const float*)d_in[8];
    float* out = (float*)d_out;

    cudaFuncSetAttribute(k_mlp, cudaFuncAttributeMaxDynamicSharedMemorySize, SMEM_TOTAL);

    k_zero_stats<<<1, 512>>>();
    k_shift_stats<<<NQ / 256, 256>>>(ffps, wsh);
    k_prep<<<4096 + NQ / 8, 256>>>(feats, bxyz, ffps, wsh, gsh, bsh);
    k_mlp<<<152, 256, SMEM_TOTAL>>>(bxyz, wmlp);
    k_finalize<<<NQ, COUT>>>(gmlp, bmlp, out);
}

// round 7
// speedup vs baseline: 2.4084x; 1.1060x over previous
#include <cuda_runtime.h>
#include <cuda_fp16.h>
#include <cstdint>
#include <math.h>

// ---------------- problem constants ----------------
#define B     4
#define N     8192
#define P     2048
#define C     128
#define COUT  256
#define S     32
#define R2    0.64f
#define EPSB  1e-5f

#define NQ    (B*P)          // 8192 queries
#define NG2   (NQ/2)         // 4096 groups of 2 queries (64 samples)
#define MLPCNT ((double)(B)*(double)(P)*(double)(S))

// smem layout (bytes). Pitch 272 B (136 halves) -> conflict-free ldmatrix.
#define OFF_WHI 0            // W hi fp16 [256][136]   69632 B
#define OFF_WLO 69632        // W lo fp16 [256][136]   69632 B
#define OFF_G   139264       // 2 bufs x Ghi[64][136] = 2 x 17408
#define GBUF    17408
#define OFF_GX  174080       // 2 bufs x 64 samples x 16 B (recentered xyz fp32)
#define SMEM_TOTAL 176128

// ---------------- device scratch ----------------
__device__ float          d_newxyz[NQ * 3];
__device__ int            d_idx[NQ * S];
__device__ unsigned short d_fhi[(size_t)B * N * C];   // fp16 of featsT (B,N,C)
__device__ float          d_mx[NQ * COUT];
__device__ float          d_mn[NQ * COUT];
__device__ double         d_sums[2 * COUT];
__device__ double         d_sst[6];
__device__ float          d_aff[2 * COUT];            // per-channel a, bb

// ---------------- PTX helpers ----------------
__device__ __forceinline__ uint32_t smem_u32(const void* p) {
    uint32_t a;
    asm("{ .reg .u64 t; cvta.to.shared.u64 t, %1; cvt.u32.u64 %0, t; }" : "=r"(a) : "l"(p));
    return a;
}
__device__ __forceinline__ void ldsm4(uint32_t* r, uint32_t addr) {
    asm volatile("ldmatrix.sync.aligned.m8n8.x4.shared.b16 {%0,%1,%2,%3}, [%4];"
                 : "=r"(r[0]), "=r"(r[1]), "=r"(r[2]), "=r"(r[3]) : "r"(addr));
}
__device__ __forceinline__ void mma16816(float* d, const uint32_t* a, const uint32_t* b) {
    asm volatile("mma.sync.aligned.m16n8k16.row.col.f32.f16.f16.f32 "
                 "{%0,%1,%2,%3}, {%4,%5,%6,%7}, {%8,%9}, {%0,%1,%2,%3};"
                 : "+f"(d[0]), "+f"(d[1]), "+f"(d[2]), "+f"(d[3])
                 : "r"(a[0]), "r"(a[1]), "r"(a[2]), "r"(a[3]), "r"(b[0]), "r"(b[1]));
}

// ---------------- kernel 0: zero stats ----------------
__global__ void k_zero_stats() {
    int t = threadIdx.x;
    if (t < 2 * COUT) d_sums[t] = 0.0;
    if (t < 6)        d_sst[t]  = 0.0;
}

// ---------------- kernel 1: shift GEMM + BN stats ----------------
__global__ void k_shift_stats(const float* __restrict__ ffps,
                              const float* __restrict__ wsh) {
    int i = blockIdx.x * blockDim.x + threadIdx.x;
    float f0 = ffps[i*3+0], f1 = ffps[i*3+1], f2 = ffps[i*3+2];
    float xs[3], xq[3];
#pragma unroll
    for (int o = 0; o < 3; o++) {
        float x = wsh[o*3+0]*f0 + wsh[o*3+1]*f1 + wsh[o*3+2]*f2;
        xs[o] = x; xq[o] = x * x;
    }
#pragma unroll
    for (int off = 16; off > 0; off >>= 1) {
#pragma unroll
        for (int o = 0; o < 3; o++) {
            xs[o] += __shfl_down_sync(0xffffffffu, xs[o], off);
            xq[o] += __shfl_down_sync(0xffffffffu, xq[o], off);
        }
    }
    if ((threadIdx.x & 31) == 0) {
#pragma unroll
        for (int o = 0; o < 3; o++) {
            atomicAdd(&d_sst[o],   (double)xs[o]);
            atomicAdd(&d_sst[3+o], (double)xq[o]);
        }
    }
}

// ---------------- kernel 2: fused prep (feature transpose + shift-apply + ball query) ----
__global__ void k_prep(const float* __restrict__ f,
                       const float* __restrict__ bxyz,
                       const float* __restrict__ ffps,
                       const float* __restrict__ wsh,
                       const float* __restrict__ gamma,
                       const float* __restrict__ beta) {
    if (blockIdx.x < 4096) {
        // ---------- transpose part ----------
        __shared__ float tile[32][33];
        int bid = blockIdx.x;
        int tx = threadIdx.x & 31, ty = threadIdx.x >> 5;
        int b  = bid >> 10;
        int c0 = ((bid >> 8) & 3) * 32;
        int n0 = (bid & 255) * 32;
        const float* src = f + ((size_t)b * C + c0) * N + n0;
#pragma unroll
        for (int r = ty; r < 32; r += 8)
            tile[r][tx] = src[(size_t)r * N + tx];
        __syncthreads();
        size_t base = ((size_t)b * N + n0) * C + c0;
#pragma unroll
        for (int r = ty; r < 32; r += 8)
            d_fhi[base + (size_t)r * C + tx] =
                __half_as_ushort(__float2half_rn(tile[tx][r]));
        return;
    }

    // ---------- ball query part ----------
    int wid  = (blockIdx.x - 4096) * 8 + (threadIdx.x >> 5);
    int lane = threadIdx.x & 31;
    int b = wid >> 11;

    float cen[3];
    {
        const float* fp = ffps + (size_t)wid * 3;
        float f0 = fp[0], f1 = fp[1], f2 = fp[2];
        double cnt = (double)NQ;
#pragma unroll
        for (int o = 0; o < 3; o++) {
            float x = wsh[o*3+0]*f0 + wsh[o*3+1]*f1 + wsh[o*3+2]*f2;
            double m = d_sst[o] / cnt;
            double v = d_sst[3+o] / cnt - m * m;
            float a = gamma[o] * rsqrtf((float)v + EPSB);
            cen[o] = fmaxf((x - (float)m) * a + beta[o], 0.0f);
        }
    }
    if (lane == 0) {
        d_newxyz[wid*3+0] = cen[0];
        d_newxyz[wid*3+1] = cen[1];
        d_newxyz[wid*3+2] = cen[2];
    }

    int* outp = d_idx + (size_t)wid * S;

    // distance lower bound: points strictly inside [-1,1); cen >= 0
    {
        float e0 = fmaxf(cen[0] - 1.0f, 0.0f);
        float e1 = fmaxf(cen[1] - 1.0f, 0.0f);
        float e2 = fmaxf(cen[2] - 1.0f, 0.0f);
        if (e0*e0 + e1*e1 + e2*e2 >= R2) {
            if (lane < S) outp[lane] = 0;
            return;
        }
    }

    const float* xb = bxyz + (size_t)b * N * 3;
    int cnt = 0, first = 0;
    bool found = false;
    for (int n0 = 0; n0 < N && cnt < S; n0 += 32) {
        int n = n0 + lane;
        float dx = xb[n*3+0] - cen[0];
        float dy = xb[n*3+1] - cen[1];
        float dz = xb[n*3+2] - cen[2];
        float d2 = dx*dx + dy*dy + dz*dz;
        unsigned m = __ballot_sync(0xffffffffu, d2 < R2);
        if (m) {
            if (!found) { found = true; first = n0 + __ffs(m) - 1; }
            bool hit = (m >> lane) & 1u;
            int pos = cnt + __popc(m & ((1u << lane) - 1u));
            if (hit && pos < S) outp[pos] = n;
            cnt += __popc(m);
        }
    }
    if (cnt > S) cnt = S;
    for (int s = cnt + lane; s < S; s += 32) outp[s] = first;
}

// ---------------- kernel 3: persistent HMMA MLP (512 threads, 16 warps) ----------------
// Warp tiling: wm = warp&7 -> M rows [wm*32, wm*32+32); wn = warp>>3 -> cols [wn*32, wn*32+32).
// 2-pass fp16 split (Whi*Ghi + Wlo*Ghi), xyz folded into the fp32 epilogue.
__global__ __launch_bounds__(512, 1)
void k_mlp(const float* __restrict__ bxyz, const float* __restrict__ wmlp) {
    extern __shared__ char smc[];
    uint32_t smb = smem_u32(smc);
    int t = threadIdx.x;
    int warp = t >> 5, lane = t & 31;
    int wm = warp & 7, wn = warp >> 3;

    // ---- W -> smem fp16 hi/lo (one time) ----
    for (int idx = t; idx < 256 * 128; idx += 512) {
        int o = idx >> 7, k = idx & 127;
        float v = wmlp[o * 131 + 3 + k];
        __half h = __float2half_rn(v);
        __half l = __float2half_rn(v - __half2float(h));
        *(__half*)(smc + OFF_WHI + o * 272 + k * 2) = h;
        *(__half*)(smc + OFF_WLO + o * 272 + k * 2) = l;
    }

    // ---- per-thread xyz weights ----
    float wx[4][3];
#pragma unroll
    for (int k = 0; k < 4; k++) {
        int o = wm * 32 + 16 * (k >> 1) + (lane >> 2) + 8 * (k & 1);
#pragma unroll
        for (int j = 0; j < 3; j++) wx[k][j] = wmlp[o * 131 + j];
    }

    // ---- ldmatrix per-thread address components ----
    int sub = lane & 7, grp = lane >> 3;
    int rowA = sub + 8 * (grp & 1);  uint32_t kA2 = (uint32_t)(grp >> 1) * 16;
    int rowB = sub + 8 * (grp >> 1); uint32_t kB2 = (uint32_t)(grp & 1) * 16;
    uint32_t aHi0 = smb + OFF_WHI + (uint32_t)(wm * 32 + rowA) * 272 + kA2;
    uint32_t aHi1 = aHi0 + 16 * 272;
    uint32_t aLo0 = aHi0 + (OFF_WLO - OFF_WHI);
    uint32_t aLo1 = aHi1 + (OFF_WLO - OFF_WHI);
    uint32_t bRow = (uint32_t)(wn * 32 + rowB) * 272 + kB2;

    // ---- prologue: gather group blockIdx.x into buffer 0 ----
    {
        int g = blockIdx.x;
        const int* idxp = d_idx + (size_t)g * 64;
        int bb = g >> 10;
        int l16 = lane & 15, hh = lane >> 4;
#pragma unroll
        for (int j = 0; j < 2; j++) {
            int s = warp * 4 + 2 * j + hh;
            int n = idxp[s];
            size_t rowo = ((size_t)bb * N + n) * C;
            uint4 uh = ((const uint4*)(d_fhi + rowo))[l16];
            *(uint4*)(smc + OFF_G + s * 272 + l16 * 16) = uh;
        }
        if (t < 64) {
            int s = t;
            int n = idxp[s];
            int q = g * 2 + (s >> 5);
            const float* cen = d_newxyz + (size_t)q * 3;
            const float* xp  = bxyz + ((size_t)bb * N + n) * 3;
            float* gp = (float*)(smc + OFF_GX + s * 16);
            gp[0] = xp[0] - cen[0];
            gp[1] = xp[1] - cen[1];
            gp[2] = xp[2] - cen[2];
        }
    }
    __syncthreads();

    float sums[4] = {0.f, 0.f, 0.f, 0.f}, sqs[4] = {0.f, 0.f, 0.f, 0.f};
    int it = 0;
    for (int g = blockIdx.x; g < NG2; g += gridDim.x, it++) {
        int p = it & 1;

        // ---- issue next group's gather LDGs (complete during MMA) ----
        int gn = g + gridDim.x;
        bool have = gn < NG2;
        uint4 gh[2];
        float px0 = 0, px1 = 0, px2 = 0, c0 = 0, c1 = 0, c2 = 0;
        if (have) {
            const int* idxp = d_idx + (size_t)gn * 64;
            int bb = gn >> 10;
            int l16 = lane & 15, hh = lane >> 4;
#pragma unroll
            for (int j = 0; j < 2; j++) {
                int s = warp * 4 + 2 * j + hh;
                int n = idxp[s];
                size_t rowo = ((size_t)bb * N + n) * C;
                gh[j] = ((const uint4*)(d_fhi + rowo))[l16];
            }
            if (t < 64) {
                int s = t;
                int n = idxp[s];
                int q = gn * 2 + (s >> 5);
                px0 = bxyz[((size_t)bb * N + n) * 3 + 0];
                px1 = bxyz[((size_t)bb * N + n) * 3 + 1];
                px2 = bxyz[((size_t)bb * N + n) * 3 + 2];
                c0 = d_newxyz[(size_t)q * 3 + 0];
                c1 = d_newxyz[(size_t)q * 3 + 1];
                c2 = d_newxyz[(size_t)q * 3 + 2];
            }
        }

        // ---- 2-pass MMA: Whi*Ghi + Wlo*Ghi ----
        float acc[2][16];
#pragma unroll
        for (int m = 0; m < 2; m++)
#pragma unroll
            for (int j = 0; j < 16; j++) acc[m][j] = 0.f;

        uint32_t bBase = smb + OFF_G + (uint32_t)p * GBUF + bRow;
#pragma unroll
        for (int ks = 0; ks < 8; ks++) {
            uint32_t kb = (uint32_t)ks * 32;
            uint32_t ah0[4], ah1[4], al0[4], al1[4], bh[8];
            ldsm4(ah0, aHi0 + kb);
            ldsm4(ah1, aHi1 + kb);
            ldsm4(al0, aLo0 + kb);
            ldsm4(al1, aLo1 + kb);
#pragma unroll
            for (int a = 0; a < 2; a++)
                ldsm4(&bh[4 * a], bBase + (uint32_t)a * 16 * 272 + kb);
#pragma unroll
            for (int m = 0; m < 2; m++) {
                uint32_t* ah = m ? ah1 : ah0;
                uint32_t* al = m ? al1 : al0;
#pragma unroll
                for (int n = 0; n < 4; n++) {
                    int bi = 4 * (n >> 1) + 2 * (n & 1);
                    mma16816(&acc[m][4 * n], ah, &bh[bi]);
                    mma16816(&acc[m][4 * n], al, &bh[bi]);
                }
            }
        }

        // ---- store gathered data into the other buffer ----
        if (have) {
            int pn = p ^ 1;
            int l16 = lane & 15, hh = lane >> 4;
#pragma unroll
            for (int j = 0; j < 2; j++) {
                int s = warp * 4 + 2 * j + hh;
                *(uint4*)(smc + OFF_G + pn * GBUF + s * 272 + l16 * 16) = gh[j];
            }
            if (t < 64) {
                int s = t;
                float* gp = (float*)(smc + OFF_GX + pn * 1024 + s * 16);
                gp[0] = px0 - c0; gp[1] = px1 - c1; gp[2] = px2 - c2;
            }
        }

        // ---- epilogue: xyz FMA + max/min + running sums (this warp: query wn) ----
        float mxq[4], mnq[4];
#pragma unroll
        for (int k = 0; k < 4; k++) { mxq[k] = -INFINITY; mnq[k] = INFINITY; }

#pragma unroll
        for (int c = 0; c < 8; c++) {
            int na = c >> 1, e = c & 1;
            int col = wn * 32 + na * 8 + 2 * (lane & 3) + e;
            const float* gp = (const float*)(smc + OFF_GX + p * 1024 + col * 16);
            float g0 = gp[0], g1 = gp[1], g2 = gp[2];
#pragma unroll
            for (int k = 0; k < 4; k++) {
                int m = k >> 1, ds = k & 1;
                float v = acc[m][na * 4 + ds * 2 + e]
                        + wx[k][0] * g0 + wx[k][1] * g1 + wx[k][2] * g2;
                mxq[k] = fmaxf(mxq[k], v);
                mnq[k] = fminf(mnq[k], v);
                sums[k] += v; sqs[k] += v * v;
            }
        }
#pragma unroll
        for (int k = 0; k < 4; k++) {
            float mx = mxq[k], mn = mnq[k];
            mx = fmaxf(mx, __shfl_xor_sync(0xffffffffu, mx, 1));
            mx = fmaxf(mx, __shfl_xor_sync(0xffffffffu, mx, 2));
            mn = fminf(mn, __shfl_xor_sync(0xffffffffu, mn, 1));
            mn = fminf(mn, __shfl_xor_sync(0xffffffffu, mn, 2));
            if ((lane & 3) == 0) {
                int o = wm * 32 + 16 * (k >> 1) + (lane >> 2) + 8 * (k & 1);
                size_t qg = (size_t)(g * 2 + wn);
                d_mx[qg * COUT + o] = mx;
                d_mn[qg * COUT + o] = mn;
            }
        }
        __syncthreads();
    }

    // ---- flush channel sums ----
#pragma unroll
    for (int k = 0; k < 4; k++) {
        float s_ = sums[k], q_ = sqs[k];
        s_ += __shfl_xor_sync(0xffffffffu, s_, 1);
        s_ += __shfl_xor_sync(0xffffffffu, s_, 2);
        q_ += __shfl_xor_sync(0xffffffffu, q_, 1);
        q_ += __shfl_xor_sync(0xffffffffu, q_, 2);
        if ((lane & 3) == 0) {
            int o = wm * 32 + 16 * (k >> 1) + (lane >> 2) + 8 * (k & 1);
            atomicAdd(&d_sums[o],        (double)s_);
            atomicAdd(&d_sums[COUT + o], (double)q_);
        }
    }
}

// ---------------- kernel 4: per-channel affine precompute ----------------
__global__ void k_affine(const float* __restrict__ gamma,
                         const float* __restrict__ beta) {
    int o = threadIdx.x;
    double m = d_sums[o] / MLPCNT;
    double v = d_sums[COUT + o] / MLPCNT - m * m;
    float a  = gamma[o] * rsqrtf((float)v + EPSB);
    d_aff[o]        = a;
    d_aff[COUT + o] = beta[o] - (float)m * a;
}

// ---------------- kernel 5: finalize ----------------
__global__ void k_finalize(float* __restrict__ out) {
    int o = threadIdx.x;
    size_t i = (size_t)blockIdx.x * COUT + o;
    float a  = d_aff[o];
    float bb = d_aff[COUT + o];
    float val = (a >= 0.0f) ? d_mx[i] : d_mn[i];
    out[i] = fmaxf(a * val + bb, 0.0f);
}

// ---------------- launch ----------------
extern "C" void kernel_launch(void* const* d_in, const int* in_sizes, int n_in,
                              void* d_out, int out_size) {
    const float* ffps  = (const float*)d_in[0];
    const float* bxyz  = (const float*)d_in[1];
    const float* feats = (const float*)d_in[2];
    const float* wsh   = (const float*)d_in[3];
    const float* gsh   = (const float*)d_in[4];
    const float* bsh   = (const float*)d_in[5];
    const float* wmlp  = (const float*)d_in[6];
    const float* gmlp  = (const float*)d_in[7];
    const float* bmlp  = (const float*)d_in[8];
    float* out = (float*)d_out;

    cudaFuncSetAttribute(k_mlp, cudaFuncAttributeMaxDynamicSharedMemorySize, SMEM_TOTAL);

    k_zero_stats<<<1, 512>>>();
    k_shift_stats<<<NQ / 256, 256>>>(ffps, wsh);
    k_prep<<<4096 + NQ / 8, 256>>>(feats, bxyz, ffps, wsh, gsh, bsh);
    k_mlp<<<152, 512, SMEM_TOTAL>>>(bxyz, wmlp);
    k_affine<<<1, COUT>>>(gmlp, bmlp);
    k_finalize<<<NQ, COUT>>>(out);
}

// round 8
// speedup vs baseline: 2.7628x; 1.1471x over previous
#include <cuda_runtime.h>
#include <cuda_fp16.h>
#include <cstdint>
#include <math.h>

// ---------------- problem constants ----------------
#define B     4
#define N     8192
#define P     2048
#define C     128
#define COUT  256
#define S     32
#define R2    0.64f
#define EPSB  1e-5f

#define NQ    (B*P)          // 8192 queries
#define NG2   (NQ/2)         // 4096 groups of 2 queries (64 samples)
#define MLPCNT ((double)(B)*(double)(P)*(double)(S))

// smem layout (bytes). Pitch 272 B (136 halves) -> conflict-free ldmatrix.
#define OFF_WHI 0            // W hi fp16 [256][136]   69632 B
#define OFF_G   69632        // 2 bufs x Ghi[64][136] = 2 x 17408
#define GBUF    17408
#define OFF_GX  104448       // 2 bufs x 64 samples x 16 B (raw xyz fp32)
#define SMEM_TOTAL 106496

// ---------------- device scratch ----------------
__device__ float          d_newxyz[NQ * 3];
__device__ int            d_idx[NQ * S];
__device__ unsigned short d_fhi[(size_t)B * N * C];   // fp16 of featsT (B,N,C)
__device__ float          d_mx[NQ * COUT];
__device__ float          d_mn[NQ * COUT];
__device__ double         d_sums[2 * COUT];
__device__ double         d_sst[6];
__device__ float          d_aff[2 * COUT];            // per-channel a, bb

// ---------------- PTX helpers ----------------
__device__ __forceinline__ uint32_t smem_u32(const void* p) {
    uint32_t a;
    asm("{ .reg .u64 t; cvta.to.shared.u64 t, %1; cvt.u32.u64 %0, t; }" : "=r"(a) : "l"(p));
    return a;
}
__device__ __forceinline__ void ldsm4(uint32_t* r, uint32_t addr) {
    asm volatile("ldmatrix.sync.aligned.m8n8.x4.shared.b16 {%0,%1,%2,%3}, [%4];"
                 : "=r"(r[0]), "=r"(r[1]), "=r"(r[2]), "=r"(r[3]) : "r"(addr));
}
__device__ __forceinline__ void mma16816(float* d, const uint32_t* a, const uint32_t* b) {
    asm volatile("mma.sync.aligned.m16n8k16.row.col.f32.f16.f16.f32 "
                 "{%0,%1,%2,%3}, {%4,%5,%6,%7}, {%8,%9}, {%0,%1,%2,%3};"
                 : "+f"(d[0]), "+f"(d[1]), "+f"(d[2]), "+f"(d[3])
                 : "r"(a[0]), "r"(a[1]), "r"(a[2]), "r"(a[3]), "r"(b[0]), "r"(b[1]));
}
__device__ __forceinline__ void cpa16(uint32_t dst, const void* src) {
    asm volatile("cp.async.cg.shared.global [%0], [%1], 16;" :: "r"(dst), "l"(src) : "memory");
}
__device__ __forceinline__ void cpa4(uint32_t dst, const void* src) {
    asm volatile("cp.async.ca.shared.global [%0], [%1], 4;" :: "r"(dst), "l"(src) : "memory");
}
#define CPASYNC_COMMIT() asm volatile("cp.async.commit_group;" ::: "memory")
#define CPASYNC_WAIT0()  asm volatile("cp.async.wait_group 0;" ::: "memory")

// ---------------- kernel 0: zero stats ----------------
__global__ void k_zero_stats() {
    int t = threadIdx.x;
    if (t < 2 * COUT) d_sums[t] = 0.0;
    if (t < 6)        d_sst[t]  = 0.0;
}

// ---------------- kernel 1: shift GEMM + BN stats ----------------
__global__ void k_shift_stats(const float* __restrict__ ffps,
                              const float* __restrict__ wsh) {
    int i = blockIdx.x * blockDim.x + threadIdx.x;
    float f0 = ffps[i*3+0], f1 = ffps[i*3+1], f2 = ffps[i*3+2];
    float xs[3], xq[3];
#pragma unroll
    for (int o = 0; o < 3; o++) {
        float x = wsh[o*3+0]*f0 + wsh[o*3+1]*f1 + wsh[o*3+2]*f2;
        xs[o] = x; xq[o] = x * x;
    }
#pragma unroll
    for (int off = 16; off > 0; off >>= 1) {
#pragma unroll
        for (int o = 0; o < 3; o++) {
            xs[o] += __shfl_down_sync(0xffffffffu, xs[o], off);
            xq[o] += __shfl_down_sync(0xffffffffu, xq[o], off);
        }
    }
    if ((threadIdx.x & 31) == 0) {
#pragma unroll
        for (int o = 0; o < 3; o++) {
            atomicAdd(&d_sst[o],   (double)xs[o]);
            atomicAdd(&d_sst[3+o], (double)xq[o]);
        }
    }
}

// ---------------- kernel 2: fused prep (feature transpose + shift-apply + ball query) ----
__global__ void k_prep(const float* __restrict__ f,
                       const float* __restrict__ bxyz,
                       const float* __restrict__ ffps,
                       const float* __restrict__ wsh,
                       const float* __restrict__ gamma,
                       const float* __restrict__ beta) {
    if (blockIdx.x < 4096) {
        // ---------- transpose part ----------
        __shared__ float tile[32][33];
        int bid = blockIdx.x;
        int tx = threadIdx.x & 31, ty = threadIdx.x >> 5;
        int b  = bid >> 10;
        int c0 = ((bid >> 8) & 3) * 32;
        int n0 = (bid & 255) * 32;
        const float* src = f + ((size_t)b * C + c0) * N + n0;
#pragma unroll
        for (int r = ty; r < 32; r += 8)
            tile[r][tx] = src[(size_t)r * N + tx];
        __syncthreads();
        size_t base = ((size_t)b * N + n0) * C + c0;
#pragma unroll
        for (int r = ty; r < 32; r += 8)
            d_fhi[base + (size_t)r * C + tx] =
                __half_as_ushort(__float2half_rn(tile[tx][r]));
        return;
    }

    // ---------- ball query part ----------
    int wid  = (blockIdx.x - 4096) * 8 + (threadIdx.x >> 5);
    int lane = threadIdx.x & 31;
    int b = wid >> 11;

    float cen[3];
    {
        const float* fp = ffps + (size_t)wid * 3;
        float f0 = fp[0], f1 = fp[1], f2 = fp[2];
        double cnt = (double)NQ;
#pragma unroll
        for (int o = 0; o < 3; o++) {
            float x = wsh[o*3+0]*f0 + wsh[o*3+1]*f1 + wsh[o*3+2]*f2;
            double m = d_sst[o] / cnt;
            double v = d_sst[3+o] / cnt - m * m;
            float a = gamma[o] * rsqrtf((float)v + EPSB);
            cen[o] = fmaxf((x - (float)m) * a + beta[o], 0.0f);
        }
    }
    if (lane == 0) {
        d_newxyz[wid*3+0] = cen[0];
        d_newxyz[wid*3+1] = cen[1];
        d_newxyz[wid*3+2] = cen[2];
    }

    int* outp = d_idx + (size_t)wid * S;

    // distance lower bound: points strictly inside [-1,1); cen >= 0
    {
        float e0 = fmaxf(cen[0] - 1.0f, 0.0f);
        float e1 = fmaxf(cen[1] - 1.0f, 0.0f);
        float e2 = fmaxf(cen[2] - 1.0f, 0.0f);
        if (e0*e0 + e1*e1 + e2*e2 >= R2) {
            if (lane < S) outp[lane] = 0;
            return;
        }
    }

    const float* xb = bxyz + (size_t)b * N * 3;
    int cnt = 0, first = 0;
    bool found = false;
    for (int n0 = 0; n0 < N && cnt < S; n0 += 32) {
        int n = n0 + lane;
        float dx = xb[n*3+0] - cen[0];
        float dy = xb[n*3+1] - cen[1];
        float dz = xb[n*3+2] - cen[2];
        float d2 = dx*dx + dy*dy + dz*dz;
        unsigned m = __ballot_sync(0xffffffffu, d2 < R2);
        if (m) {
            if (!found) { found = true; first = n0 + __ffs(m) - 1; }
            bool hit = (m >> lane) & 1u;
            int pos = cnt + __popc(m & ((1u << lane) - 1u));
            if (hit && pos < S) outp[pos] = n;
            cnt += __popc(m);
        }
    }
    if (cnt > S) cnt = S;
    for (int s = cnt + lane; s < S; s += 32) outp[s] = first;
}

// ---- async gather of group gg into buffer pb (features + raw xyz) ----
__device__ __forceinline__ void gather_async(uint32_t smb, const char* smc_unused,
                                             int gg, int pb,
                                             int warp, int lane, int t,
                                             const float* bxyz) {
    const int* idxp = d_idx + (size_t)gg * 64;
    int bb = gg >> 10;
    int l16 = lane & 15, hh = lane >> 4;
#pragma unroll
    for (int j = 0; j < 2; j++) {
        int s = warp * 4 + 2 * j + hh;
        int n = idxp[s];
        const char* src = (const char*)(d_fhi + ((size_t)bb * N + n) * C) + l16 * 16;
        cpa16(smb + OFF_G + (uint32_t)pb * GBUF + (uint32_t)s * 272 + (uint32_t)l16 * 16, src);
    }
    if (t < 64) {
        int n = idxp[t];
        const float* xp = bxyz + ((size_t)bb * N + n) * 3;
        uint32_t dst = smb + OFF_GX + (uint32_t)pb * 1024 + (uint32_t)t * 16;
        cpa4(dst + 0, xp + 0);
        cpa4(dst + 4, xp + 1);
        cpa4(dst + 8, xp + 2);
    }
}

// ---------------- kernel 3: persistent HMMA MLP (512 threads, 16 warps) ----------------
// Single-pass fp16, W fragments hoisted to registers, cp.async gather pipeline.
// Warp tiling: wm = warp&7 -> M rows [wm*32,+32); wn = warp>>3 -> cols [wn*32,+32).
__global__ __launch_bounds__(512, 1)
void k_mlp(const float* __restrict__ bxyz, const float* __restrict__ wmlp) {
    extern __shared__ char smc[];
    uint32_t smb = smem_u32(smc);
    int t = threadIdx.x;
    int warp = t >> 5, lane = t & 31;
    int wm = warp & 7, wn = warp >> 3;

    // ---- W -> smem fp16 (one time) ----
    for (int idx = t; idx < 256 * 128; idx += 512) {
        int o = idx >> 7, k = idx & 127;
        *(__half*)(smc + OFF_WHI + o * 272 + k * 2) =
            __float2half_rn(wmlp[o * 131 + 3 + k]);
    }

    // ---- per-thread xyz weights ----
    float wx[4][3];
#pragma unroll
    for (int k = 0; k < 4; k++) {
        int o = wm * 32 + 16 * (k >> 1) + (lane >> 2) + 8 * (k & 1);
#pragma unroll
        for (int j = 0; j < 3; j++) wx[k][j] = wmlp[o * 131 + j];
    }

    // ---- ldmatrix per-thread address components ----
    int sub = lane & 7, grp = lane >> 3;
    int rowA = sub + 8 * (grp & 1);  uint32_t kA2 = (uint32_t)(grp >> 1) * 16;
    int rowB = sub + 8 * (grp >> 1); uint32_t kB2 = (uint32_t)(grp & 1) * 16;
    uint32_t aHi0 = smb + OFF_WHI + (uint32_t)(wm * 32 + rowA) * 272 + kA2;
    uint32_t aHi1 = aHi0 + 16 * 272;
    uint32_t bRow = (uint32_t)(wn * 32 + rowB) * 272 + kB2;

    // ---- prologue: async gather of first group into buffer 0 ----
    gather_async(smb, smc, blockIdx.x, 0, warp, lane, t, bxyz);
    CPASYNC_COMMIT();
    CPASYNC_WAIT0();
    __syncthreads();

    // ---- hoist A (W) fragments into registers: loop-invariant ----
    uint32_t ah[64];
#pragma unroll
    for (int ks = 0; ks < 8; ks++) {
        ldsm4(&ah[ks * 8 + 0], aHi0 + (uint32_t)ks * 32);
        ldsm4(&ah[ks * 8 + 4], aHi1 + (uint32_t)ks * 32);
    }

    float sums[4] = {0.f, 0.f, 0.f, 0.f}, sqs[4] = {0.f, 0.f, 0.f, 0.f};
    int it = 0;
    for (int g = blockIdx.x; g < NG2; g += gridDim.x, it++) {
        int p = it & 1, pn = p ^ 1;

        // ---- issue next group's gather (lands during MMA) ----
        int gn = g + gridDim.x;
        if (gn < NG2) gather_async(smb, smc, gn, pn, warp, lane, t, bxyz);
        CPASYNC_COMMIT();

        // ---- single-pass MMA: Whi * Ghi ----
        float acc[32];
#pragma unroll
        for (int j = 0; j < 32; j++) acc[j] = 0.f;

        uint32_t bBase = smb + OFF_G + (uint32_t)p * GBUF + bRow;
#pragma unroll
        for (int ks = 0; ks < 8; ks++) {
            uint32_t kb = (uint32_t)ks * 32;
            uint32_t bh[8];
            ldsm4(&bh[0], bBase + kb);
            ldsm4(&bh[4], bBase + 16 * 272 + kb);
#pragma unroll
            for (int m = 0; m < 2; m++)
#pragma unroll
                for (int n = 0; n < 4; n++) {
                    int bi = 4 * (n >> 1) + 2 * (n & 1);
                    mma16816(&acc[m * 16 + 4 * n], &ah[ks * 8 + 4 * m], &bh[bi]);
                }
        }

        // ---- epilogue: recenter xyz + FMA + max/min + running sums ----
        float c0 = d_newxyz[(size_t)(g * 2 + wn) * 3 + 0];
        float c1 = d_newxyz[(size_t)(g * 2 + wn) * 3 + 1];
        float c2 = d_newxyz[(size_t)(g * 2 + wn) * 3 + 2];

        float mxq[4], mnq[4];
#pragma unroll
        for (int k = 0; k < 4; k++) { mxq[k] = -INFINITY; mnq[k] = INFINITY; }

#pragma unroll
        for (int c = 0; c < 8; c++) {
            int na = c >> 1, e = c & 1;
            int col = wn * 32 + na * 8 + 2 * (lane & 3) + e;
            const float* gp = (const float*)(smc + OFF_GX + p * 1024 + col * 16);
            float g0 = gp[0] - c0, g1 = gp[1] - c1, g2 = gp[2] - c2;
#pragma unroll
            for (int k = 0; k < 4; k++) {
                int m = k >> 1, ds = k & 1;
                float v = acc[m * 16 + na * 4 + ds * 2 + e]
                        + wx[k][0] * g0 + wx[k][1] * g1 + wx[k][2] * g2;
                mxq[k] = fmaxf(mxq[k], v);
                mnq[k] = fminf(mnq[k], v);
                sums[k] += v; sqs[k] += v * v;
            }
        }
#pragma unroll
        for (int k = 0; k < 4; k++) {
            float mx = mxq[k], mn = mnq[k];
            mx = fmaxf(mx, __shfl_xor_sync(0xffffffffu, mx, 1));
            mx = fmaxf(mx, __shfl_xor_sync(0xffffffffu, mx, 2));
            mn = fminf(mn, __shfl_xor_sync(0xffffffffu, mn, 1));
            mn = fminf(mn, __shfl_xor_sync(0xffffffffu, mn, 2));
            if ((lane & 3) == 0) {
                int o = wm * 32 + 16 * (k >> 1) + (lane >> 2) + 8 * (k & 1);
                size_t qg = (size_t)(g * 2 + wn);
                d_mx[qg * COUT + o] = mx;
                d_mn[qg * COUT + o] = mn;
            }
        }

        CPASYNC_WAIT0();
        __syncthreads();
    }

    // ---- flush channel sums ----
#pragma unroll
    for (int k = 0; k < 4; k++) {
        float s_ = sums[k], q_ = sqs[k];
        s_ += __shfl_xor_sync(0xffffffffu, s_, 1);
        s_ += __shfl_xor_sync(0xffffffffu, s_, 2);
        q_ += __shfl_xor_sync(0xffffffffu, q_, 1);
        q_ += __shfl_xor_sync(0xffffffffu, q_, 2);
        if ((lane & 3) == 0) {
            int o = wm * 32 + 16 * (k >> 1) + (lane >> 2) + 8 * (k & 1);
            atomicAdd(&d_sums[o],        (double)s_);
            atomicAdd(&d_sums[COUT + o], (double)q_);
        }
    }
}

// ---------------- kernel 4: per-channel affine precompute ----------------
__global__ void k_affine(const float* __restrict__ gamma,
                         const float* __restrict__ beta) {
    int o = threadIdx.x;
    double m = d_sums[o] / MLPCNT;
    double v = d_sums[COUT + o] / MLPCNT - m * m;
    float a  = gamma[o] * rsqrtf((float)v + EPSB);
    d_aff[o]        = a;
    d_aff[COUT + o] = beta[o] - (float)m * a;
}

// ---------------- kernel 5: finalize ----------------
__global__ void k_finalize(float* __restrict__ out) {
    int o = threadIdx.x;
    size_t i = (size_t)blockIdx.x * COUT + o;
    float a  = d_aff[o];
    float bb = d_aff[COUT + o];
    float val = (a >= 0.0f) ? d_mx[i] : d_mn[i];
    out[i] = fmaxf(a * val + bb, 0.0f);
}

// ---------------- launch ----------------
extern "C" void kernel_launch(void* const* d_in, const int* in_sizes, int n_in,
                              void* d_out, int out_size) {
    const float* ffps  = (const float*)d_in[0];
    const float* bxyz  = (const float*)d_in[1];
    const float* feats = (const float*)d_in[2];
    const float* wsh   = (const float*)d_in[3];
    const float* gsh   = (const float*)d_in[4];
    const float* bsh   = (const float*)d_in[5];
    const float* wmlp  = (const float*)d_in[6];
    const float* gmlp  = (const float*)d_in[7];
    const float* bmlp  = (const float*)d_in[8];
    float* out = (float*)d_out;

    cudaFuncSetAttribute(k_mlp, cudaFuncAttributeMaxDynamicSharedMemorySize, SMEM_TOTAL);

    k_zero_stats<<<1, 512>>>();
    k_shift_stats<<<NQ / 256, 256>>>(ffps, wsh);
    k_prep<<<4096 + NQ / 8, 256>>>(feats, bxyz, ffps, wsh, gsh, bsh);
    k_mlp<<<152, 512, SMEM_TOTAL>>>(bxyz, wmlp);
    k_affine<<<1, COUT>>>(gmlp, bmlp);
    k_finalize<<<NQ, COUT>>>(out);
}

// round 9
// speedup vs baseline: 3.1716x; 1.1480x over previous
#include <cuda_runtime.h>
#include <cuda_fp16.h>
#include <cstdint>
#include <math.h>

// ---------------- problem constants ----------------
#define B     4
#define N     8192
#define P     2048
#define C     128
#define COUT  256
#define S     32
#define R2    0.64f
#define EPSB  1e-5f

#define NQ    (B*P)          // 8192 queries
#define NG2   (NQ/2)         // 4096 groups of 2 queries (64 samples)
#define MLPCNT ((double)(B)*(double)(P)*(double)(S))

// smem layout (bytes). Pitch 304 B (152 halves): 76 words -> 8 ldsm rows hit
// distinct banks (12i mod 32 distinct for i=0..7). K: 0..127 feats, 128..130 xyz,
// 131..143 zero pad (ks=8 reads k 128..143).
#define WPITCH  304
#define OFF_W   0                     // W fp16 [256][152]  77824 B
#define OFF_G   77824                 // 2 bufs x G[64][152] = 2 x 19456
#define GBUF    19456
#define SMEM_TOTAL (77824 + 2*19456)  // 116736

// ---------------- device scratch ----------------
__device__ float          d_newxyz[NQ * 3];
__device__ int            d_idx[NQ * S];
__device__ unsigned short d_fhi[(size_t)B * N * C];   // fp16 of featsT (B,N,C)
__device__ float          d_mx[NQ * COUT];
__device__ double         d_sums[2 * COUT];
__device__ double         d_sst[6];
__device__ float          d_aff[2 * COUT];            // per-channel a, bb

// ---------------- PTX helpers ----------------
__device__ __forceinline__ uint32_t smem_u32(const void* p) {
    uint32_t a;
    asm("{ .reg .u64 t; cvta.to.shared.u64 t, %1; cvt.u32.u64 %0, t; }" : "=r"(a) : "l"(p));
    return a;
}
__device__ __forceinline__ void ldsm4(uint32_t* r, uint32_t addr) {
    asm volatile("ldmatrix.sync.aligned.m8n8.x4.shared.b16 {%0,%1,%2,%3}, [%4];"
                 : "=r"(r[0]), "=r"(r[1]), "=r"(r[2]), "=r"(r[3]) : "r"(addr));
}
__device__ __forceinline__ void mma16816(float* d, const uint32_t* a, const uint32_t* b) {
    asm volatile("mma.sync.aligned.m16n8k16.row.col.f32.f16.f16.f32 "
                 "{%0,%1,%2,%3}, {%4,%5,%6,%7}, {%8,%9}, {%0,%1,%2,%3};"
                 : "+f"(d[0]), "+f"(d[1]), "+f"(d[2]), "+f"(d[3])
                 : "r"(a[0]), "r"(a[1]), "r"(a[2]), "r"(a[3]), "r"(b[0]), "r"(b[1]));
}
__device__ __forceinline__ void cpa16(uint32_t dst, const void* src) {
    asm volatile("cp.async.cg.shared.global [%0], [%1], 16;" :: "r"(dst), "l"(src) : "memory");
}
#define CPASYNC_COMMIT() asm volatile("cp.async.commit_group;" ::: "memory")
#define CPASYNC_WAIT0()  asm volatile("cp.async.wait_group 0;" ::: "memory")

// ---------------- kernel 0: zero stats ----------------
__global__ void k_zero_stats() {
    int t = threadIdx.x;
    if (t < 2 * COUT) d_sums[t] = 0.0;
    if (t < 6)        d_sst[t]  = 0.0;
}

// ---------------- kernel 1: shift GEMM + BN stats ----------------
__global__ void k_shift_stats(const float* __restrict__ ffps,
                              const float* __restrict__ wsh) {
    int i = blockIdx.x * blockDim.x + threadIdx.x;
    float f0 = ffps[i*3+0], f1 = ffps[i*3+1], f2 = ffps[i*3+2];
    float xs[3], xq[3];
#pragma unroll
    for (int o = 0; o < 3; o++) {
        float x = wsh[o*3+0]*f0 + wsh[o*3+1]*f1 + wsh[o*3+2]*f2;
        xs[o] = x; xq[o] = x * x;
    }
#pragma unroll
    for (int off = 16; off > 0; off >>= 1) {
#pragma unroll
        for (int o = 0; o < 3; o++) {
            xs[o] += __shfl_down_sync(0xffffffffu, xs[o], off);
            xq[o] += __shfl_down_sync(0xffffffffu, xq[o], off);
        }
    }
    if ((threadIdx.x & 31) == 0) {
#pragma unroll
        for (int o = 0; o < 3; o++) {
            atomicAdd(&d_sst[o],   (double)xs[o]);
            atomicAdd(&d_sst[3+o], (double)xq[o]);
        }
    }
}

// ---------------- kernel 2: fused prep (feature transpose + shift-apply + ball query) ----
__global__ void k_prep(const float* __restrict__ f,
                       const float* __restrict__ bxyz,
                       const float* __restrict__ ffps,
                       const float* __restrict__ wsh,
                       const float* __restrict__ gamma,
                       const float* __restrict__ beta) {
    if (blockIdx.x < 4096) {
        // ---------- transpose part ----------
        __shared__ float tile[32][33];
        int bid = blockIdx.x;
        int tx = threadIdx.x & 31, ty = threadIdx.x >> 5;
        int b  = bid >> 10;
        int c0 = ((bid >> 8) & 3) * 32;
        int n0 = (bid & 255) * 32;
        const float* src = f + ((size_t)b * C + c0) * N + n0;
#pragma unroll
        for (int r = ty; r < 32; r += 8)
            tile[r][tx] = src[(size_t)r * N + tx];
        __syncthreads();
        size_t base = ((size_t)b * N + n0) * C + c0;
#pragma unroll
        for (int r = ty; r < 32; r += 8)
            d_fhi[base + (size_t)r * C + tx] =
                __half_as_ushort(__float2half_rn(tile[tx][r]));
        return;
    }

    // ---------- ball query part ----------
    int wid  = (blockIdx.x - 4096) * 8 + (threadIdx.x >> 5);
    int lane = threadIdx.x & 31;
    int b = wid >> 11;

    float cen[3];
    {
        const float* fp = ffps + (size_t)wid * 3;
        float f0 = fp[0], f1 = fp[1], f2 = fp[2];
        double cnt = (double)NQ;
#pragma unroll
        for (int o = 0; o < 3; o++) {
            float x = wsh[o*3+0]*f0 + wsh[o*3+1]*f1 + wsh[o*3+2]*f2;
            double m = d_sst[o] / cnt;
            double v = d_sst[3+o] / cnt - m * m;
            float a = gamma[o] * rsqrtf((float)v + EPSB);
            cen[o] = fmaxf((x - (float)m) * a + beta[o], 0.0f);
        }
    }
    if (lane == 0) {
        d_newxyz[wid*3+0] = cen[0];
        d_newxyz[wid*3+1] = cen[1];
        d_newxyz[wid*3+2] = cen[2];
    }

    int* outp = d_idx + (size_t)wid * S;

    // distance lower bound: points strictly inside [-1,1); cen >= 0
    {
        float e0 = fmaxf(cen[0] - 1.0f, 0.0f);
        float e1 = fmaxf(cen[1] - 1.0f, 0.0f);
        float e2 = fmaxf(cen[2] - 1.0f, 0.0f);
        if (e0*e0 + e1*e1 + e2*e2 >= R2) {
            if (lane < S) outp[lane] = 0;
            return;
        }
    }

    const float* xb = bxyz + (size_t)b * N * 3;
    int cnt = 0, first = 0;
    bool found = false;
    for (int n0 = 0; n0 < N && cnt < S; n0 += 32) {
        int n = n0 + lane;
        float dx = xb[n*3+0] - cen[0];
        float dy = xb[n*3+1] - cen[1];
        float dz = xb[n*3+2] - cen[2];
        float d2 = dx*dx + dy*dy + dz*dz;
        unsigned m = __ballot_sync(0xffffffffu, d2 < R2);
        if (m) {
            if (!found) { found = true; first = n0 + __ffs(m) - 1; }
            bool hit = (m >> lane) & 1u;
            int pos = cnt + __popc(m & ((1u << lane) - 1u));
            if (hit && pos < S) outp[pos] = n;
            cnt += __popc(m);
        }
    }
    if (cnt > S) cnt = S;
    for (int s = cnt + lane; s < S; s += 32) outp[s] = first;
}

// ---- async gather of group gg into buffer pb: features via cp.async,
// ---- recentered xyz fp16 into K-channels 128..130 via STS.
__device__ __forceinline__ void gather_async(uint32_t smb, char* smc,
                                             int gg, int pb,
                                             int warp, int lane, int t,
                                             const float* bxyz) {
    const int* idxp = d_idx + (size_t)gg * 64;
    int bb = gg >> 10;
    int l16 = lane & 15, hh = lane >> 4;
#pragma unroll
    for (int j = 0; j < 2; j++) {
        int s = warp * 4 + 2 * j + hh;
        int n = idxp[s];
        const char* src = (const char*)(d_fhi + ((size_t)bb * N + n) * C) + l16 * 16;
        cpa16(smb + OFF_G + (uint32_t)pb * GBUF + (uint32_t)s * WPITCH + (uint32_t)l16 * 16, src);
    }
    if (t < 64) {
        int n = idxp[t];
        int q = gg * 2 + (t >> 5);
        const float* cen = d_newxyz + (size_t)q * 3;
        const float* xp  = bxyz + ((size_t)bb * N + n) * 3;
        __half hx = __float2half_rn(xp[0] - cen[0]);
        __half hy = __float2half_rn(xp[1] - cen[1]);
        __half hz = __float2half_rn(xp[2] - cen[2]);
        char* dst = smc + OFF_G + (size_t)pb * GBUF + (size_t)t * WPITCH + 256;
        uint32_t xy = (uint32_t)__half_as_ushort(hx) |
                      ((uint32_t)__half_as_ushort(hy) << 16);
        *(uint32_t*)dst = xy;                   // k=128,129
        *(__half*)(dst + 4) = hz;               // k=130
    }
}

// ---------------- kernel 3: persistent HMMA MLP (512 threads, 16 warps) ----------------
// Single-pass fp16, K=144 (feats 0..127, xyz 128..130, pad 131..143 zero).
// Warp tiling: wm = warp&7 -> M rows [wm*32,+32); wn = warp>>3 -> query wn of the group.
// A (W) fragments ks 0..7 hoisted to regs; ks 8 loaded from smem per group.
// Epilogue: max + sum + sumsq only (gamma_mlp > 0, so min path never selected).
__global__ __launch_bounds__(512, 1)
void k_mlp(const float* __restrict__ bxyz, const float* __restrict__ wmlp) {
    extern __shared__ char smc[];
    uint32_t smb = smem_u32(smc);
    int t = threadIdx.x;
    int warp = t >> 5, lane = t & 31;
    int wm = warp & 7, wn = warp >> 3;

    // ---- zero W + G areas (pad columns must be 0) ----
    for (uint32_t off = (uint32_t)t * 16; off < SMEM_TOTAL; off += 512u * 16)
        *(uint4*)(smc + off) = make_uint4(0, 0, 0, 0);
    __syncthreads();

    // ---- W -> smem fp16, K-permuted: feats at 0..127, xyz at 128..130 ----
    for (int idx = t; idx < 256 * 131; idx += 512) {
        int o = idx / 131, k = idx % 131;
        int kk = (k < 3) ? (128 + k) : (k - 3);
        *(__half*)(smc + OFF_W + o * WPITCH + kk * 2) =
            __float2half_rn(wmlp[o * 131 + k]);
    }

    // ---- ldmatrix per-thread address components ----
    int sub = lane & 7, grp = lane >> 3;
    int rowA = sub + 8 * (grp & 1);  uint32_t kA2 = (uint32_t)(grp >> 1) * 16;
    int rowB = sub + 8 * (grp >> 1); uint32_t kB2 = (uint32_t)(grp & 1) * 16;
    uint32_t aHi0 = smb + OFF_W + (uint32_t)(wm * 32 + rowA) * WPITCH + kA2;
    uint32_t aHi1 = aHi0 + 16 * WPITCH;
    uint32_t bRow = (uint32_t)(wn * 32 + rowB) * WPITCH + kB2;

    // ---- prologue: async gather of first group into buffer 0 ----
    gather_async(smb, smc, blockIdx.x, 0, warp, lane, t, bxyz);
    CPASYNC_COMMIT();
    CPASYNC_WAIT0();
    __syncthreads();

    // ---- hoist A (W) fragments ks 0..7 into registers (loop-invariant) ----
    uint32_t ah[64];
#pragma unroll
    for (int ks = 0; ks < 8; ks++) {
        ldsm4(&ah[ks * 8 + 0], aHi0 + (uint32_t)ks * 32);
        ldsm4(&ah[ks * 8 + 4], aHi1 + (uint32_t)ks * 32);
    }

    float sums[4] = {0.f, 0.f, 0.f, 0.f}, sqs[4] = {0.f, 0.f, 0.f, 0.f};
    int it = 0;
    for (int g = blockIdx.x; g < NG2; g += gridDim.x, it++) {
        int p = it & 1, pn = p ^ 1;

        // ---- issue next group's gather (lands during MMA) ----
        int gn = g + gridDim.x;
        if (gn < NG2) gather_async(smb, smc, gn, pn, warp, lane, t, bxyz);
        CPASYNC_COMMIT();

        // ---- single-pass MMA over K=144 (9 K-steps) ----
        float acc[32];
#pragma unroll
        for (int j = 0; j < 32; j++) acc[j] = 0.f;

        uint32_t bBase = smb + OFF_G + (uint32_t)p * GBUF + bRow;
#pragma unroll
        for (int ks = 0; ks < 8; ks++) {
            uint32_t kb = (uint32_t)ks * 32;
            uint32_t bh[8];
            ldsm4(&bh[0], bBase + kb);
            ldsm4(&bh[4], bBase + 16 * WPITCH + kb);
#pragma unroll
            for (int m = 0; m < 2; m++)
#pragma unroll
                for (int n = 0; n < 4; n++) {
                    int bi = 4 * (n >> 1) + 2 * (n & 1);
                    mma16816(&acc[m * 16 + 4 * n], &ah[ks * 8 + 4 * m], &bh[bi]);
                }
        }
        {   // ks = 8 (xyz + pad), A from smem
            uint32_t a8[8], bh[8];
            ldsm4(&a8[0], aHi0 + 256);
            ldsm4(&a8[4], aHi1 + 256);
            ldsm4(&bh[0], bBase + 256);
            ldsm4(&bh[4], bBase + 16 * WPITCH + 256);
#pragma unroll
            for (int m = 0; m < 2; m++)
#pragma unroll
                for (int n = 0; n < 4; n++) {
                    int bi = 4 * (n >> 1) + 2 * (n & 1);
                    mma16816(&acc[m * 16 + 4 * n], &a8[4 * m], &bh[bi]);
                }
        }

        // ---- epilogue: max + sum + sumsq (3 ops per value) ----
        float mxq[4];
#pragma unroll
        for (int k = 0; k < 4; k++) mxq[k] = -INFINITY;
#pragma unroll
        for (int k = 0; k < 4; k++) {
            int m = k >> 1, ds = k & 1;
#pragma unroll
            for (int na = 0; na < 4; na++)
#pragma unroll
                for (int e = 0; e < 2; e++) {
                    float v = acc[m * 16 + na * 4 + ds * 2 + e];
                    mxq[k] = fmaxf(mxq[k], v);
                    sums[k] += v;
                    sqs[k] = fmaf(v, v, sqs[k]);
                }
        }
#pragma unroll
        for (int k = 0; k < 4; k++) {
            float mx = mxq[k];
            mx = fmaxf(mx, __shfl_xor_sync(0xffffffffu, mx, 1));
            mx = fmaxf(mx, __shfl_xor_sync(0xffffffffu, mx, 2));
            if ((lane & 3) == 0) {
                int o = wm * 32 + 16 * (k >> 1) + (lane >> 2) + 8 * (k & 1);
                d_mx[(size_t)(g * 2 + wn) * COUT + o] = mx;
            }
        }

        CPASYNC_WAIT0();
        __syncthreads();
    }

    // ---- flush channel sums ----
#pragma unroll
    for (int k = 0; k < 4; k++) {
        float s_ = sums[k], q_ = sqs[k];
        s_ += __shfl_xor_sync(0xffffffffu, s_, 1);
        s_ += __shfl_xor_sync(0xffffffffu, s_, 2);
        q_ += __shfl_xor_sync(0xffffffffu, q_, 1);
        q_ += __shfl_xor_sync(0xffffffffu, q_, 2);
        if ((lane & 3) == 0) {
            int o = wm * 32 + 16 * (k >> 1) + (lane >> 2) + 8 * (k & 1);
            atomicAdd(&d_sums[o],        (double)s_);
            atomicAdd(&d_sums[COUT + o], (double)q_);
        }
    }
}

// ---------------- kernel 4: per-channel affine precompute ----------------
__global__ void k_affine(const float* __restrict__ gamma,
                         const float* __restrict__ beta) {
    int o = threadIdx.x;
    double m = d_sums[o] / MLPCNT;
    double v = d_sums[COUT + o] / MLPCNT - m * m;
    float a  = gamma[o] * rsqrtf((float)v + EPSB);
    d_aff[o]        = a;
    d_aff[COUT + o] = beta[o] - (float)m * a;
}

// ---------------- kernel 5: finalize (gamma > 0 -> max branch always) ----------------
__global__ void k_finalize(float* __restrict__ out) {
    int o = threadIdx.x;
    size_t i = (size_t)blockIdx.x * COUT + o;
    out[i] = fmaxf(d_aff[o] * d_mx[i] + d_aff[COUT + o], 0.0f);
}

// ---------------- launch ----------------
extern "C" void kernel_launch(void* const* d_in, const int* in_sizes, int n_in,
                              void* d_out, int out_size) {
    const float* ffps  = (const float*)d_in[0];
    const float* bxyz  = (const float*)d_in[1];
    const float* feats = (const float*)d_in[2];
    const float* wsh   = (const float*)d_in[3];
    const float* gsh   = (const float*)d_in[4];
    const float* bsh   = (const float*)d_in[5];
    const float* wmlp  = (const float*)d_in[6];
    const float* gmlp  = (const float*)d_in[7];
    const float* bmlp  = (const float*)d_in[8];
    float* out = (float*)d_out;

    cudaFuncSetAttribute(k_mlp, cudaFuncAttributeMaxDynamicSharedMemorySize, SMEM_TOTAL);

    k_zero_stats<<<1, 512>>>();
    k_shift_stats<<<NQ / 256, 256>>>(ffps, wsh);
    k_prep<<<4096 + NQ / 8, 256>>>(feats, bxyz, ffps, wsh, gsh, bsh);
    k_mlp<<<152, 512, SMEM_TOTAL>>>(bxyz, wmlp);
    k_affine<<<1, COUT>>>(gmlp, bmlp);
    k_finalize<<<NQ, COUT>>>(out);
}